// round 6
// baseline (speedup 1.0000x reference)
#include <cuda_runtime.h>
#include <cuda_bf16.h>

#define B_ 64
#define S_ 512
#define I_ 512
#define H_ 1024
#define O_ 512

// ---------------------------------------------------------------------------
// Static device scratch (no allocations anywhere)
// ---------------------------------------------------------------------------
__device__ float g_U[(S_ - 1) * B_ * H_];   // U[t][b][j]; later reused as logits[r][o]
__device__ float g_Z[B_ * S_ * H_];         // Z[b][t][j]; t=0 slice stays .bss zero forever
__device__ float g_hbuf[2][B_ * H_];        // ping-pong hidden state
__device__ unsigned g_bar;                  // grid barrier counter

// ---------------------------------------------------------------------------
// f32x2 packed fp32 helpers (sm_100+): 2 fp32 MACs per issued instruction.
// ---------------------------------------------------------------------------
static __device__ __forceinline__ void ffma2(unsigned long long& d,
                                             unsigned long long a,
                                             unsigned long long b) {
    asm("fma.rn.f32x2 %0, %1, %2, %0;" : "+l"(d) : "l"(a), "l"(b));
}
static __device__ __forceinline__ unsigned long long pk(float x, float y) {
    unsigned long long r;
    asm("mov.b64 %0, {%1,%2};" : "=l"(r) : "f"(x), "f"(y));
    return r;
}
static __device__ __forceinline__ float2 unpk(unsigned long long v) {
    float2 r;
    asm("mov.b64 {%0,%1}, %2;" : "=f"(r.x), "=f"(r.y) : "l"(v));
    return r;
}

// ---------------------------------------------------------------------------
// Init: h0 -> g_hbuf[0], reset barrier counter
// ---------------------------------------------------------------------------
__global__ void init_k(const float* __restrict__ h0) {
    int i = blockIdx.x * blockDim.x + threadIdx.x;
    if (i < B_ * H_) g_hbuf[0][i] = h0[i];
    if (i == 0) g_bar = 0u;
}

// ---------------------------------------------------------------------------
// GEMM v3: 64x64 tile, 256 threads. A duplicated in SMEM at store time so
// the inner loop has ZERO operand-duplication MOVs:
//   per kk: 2 LDS.128 (dup-a pairs) + 1 LDS.128 (w pairs) + 8 FFMA2
//   = 11 issue slots per 16 FMA-pipe cycles.
// acc[r][c] holds rows r (ty*4+r), col pair (tx*4+2c, +2c+1).
//   MODE 0: U = x[:, t, :] @ Wi^T + bi       (y = t in 0..510, K=512,  N=1024)
//   MODE 1: logits = Z @ W3^T + b3           (y = row-tile,   K=1024, N=512)
// ---------------------------------------------------------------------------
template <int MODE>
__global__ __launch_bounds__(256) void gemm_k(const float* __restrict__ A,
                                              const float* __restrict__ W,
                                              const float* __restrict__ bias) {
    constexpr int K = (MODE == 0) ? I_ : H_;
    constexpr int N = (MODE == 0) ? H_ : O_;

    __shared__ float As2[16][132];   // duplicated a: [kk][2*row], 132 = 16B-aligned rows
    __shared__ float Ws[16][68];

    const int tid = threadIdx.x;
    const int n0 = blockIdx.x * 64;
    const int y  = blockIdx.y;
    const int lm = tid >> 2;        // 0..63 row for loads
    const int kq = (tid & 3) << 2;  // 0,4,8,12

    const int tx = tid & 15;        // 4-col group (cols tx*4..+3)
    const int ty = tid >> 4;        // 4-row group (rows ty*4..+3)

    unsigned long long acc[4][2];
#pragma unroll
    for (int r = 0; r < 4; ++r) { acc[r][0] = 0ull; acc[r][1] = 0ull; }

    for (int k0 = 0; k0 < K; k0 += 16) {
        float4 av;
        if (MODE == 0) {
            av = *(const float4*)&A[((lm << 9) + y) * I_ + k0 + kq];
        } else {
            av = *(const float4*)&g_Z[((y << 6) + lm) * H_ + k0 + kq];
        }
        float4 wv = *(const float4*)&W[(n0 + lm) * K + k0 + kq];
        *(float2*)&As2[kq + 0][lm << 1] = make_float2(av.x, av.x);
        *(float2*)&As2[kq + 1][lm << 1] = make_float2(av.y, av.y);
        *(float2*)&As2[kq + 2][lm << 1] = make_float2(av.z, av.z);
        *(float2*)&As2[kq + 3][lm << 1] = make_float2(av.w, av.w);
        Ws[kq + 0][lm] = wv.x; Ws[kq + 1][lm] = wv.y;
        Ws[kq + 2][lm] = wv.z; Ws[kq + 3][lm] = wv.w;
        __syncthreads();

#pragma unroll
        for (int kk = 0; kk < 16; ++kk) {
            ulonglong2 a01 = *(const ulonglong2*)&As2[kk][ty << 3];       // (a0,a0),(a1,a1)
            ulonglong2 a23 = *(const ulonglong2*)&As2[kk][(ty << 3) + 4]; // (a2,a2),(a3,a3)
            ulonglong2 wp  = *(const ulonglong2*)&Ws[kk][tx << 2];        // (w0,w1),(w2,w3)
            ffma2(acc[0][0], a01.x, wp.x); ffma2(acc[0][1], a01.x, wp.y);
            ffma2(acc[1][0], a01.y, wp.x); ffma2(acc[1][1], a01.y, wp.y);
            ffma2(acc[2][0], a23.x, wp.x); ffma2(acc[2][1], a23.x, wp.y);
            ffma2(acc[3][0], a23.y, wp.x); ffma2(acc[3][1], a23.y, wp.y);
        }
        __syncthreads();
    }

    const float4 b4 = *(const float4*)&bias[n0 + (tx << 2)];
#pragma unroll
    for (int r = 0; r < 4; ++r) {
        float2 p0 = unpk(acc[r][0]);   // cols tx*4+0, +1
        float2 p1 = unpk(acc[r][1]);   // cols tx*4+2, +3
        float4 o = make_float4(p0.x + b4.x, p0.y + b4.y, p1.x + b4.z, p1.y + b4.w);
        long rg = (long)((y << 6) + (ty << 2) + r);
        *(float4*)&g_U[rg * N + n0 + (tx << 2)] = o;
    }
}

// ---------------------------------------------------------------------------
// Persistent recurrence kernel v5:
//  - 512 threads (16 warps = 4/SMSP), 128 CTAs = 4 b-groups x 32 j-groups
//  - warp w owns k-slice [w*64, w*64+64); lane l owns j = j0 + l
//  - Wh[j][k-slice] in 32 f32x2 registers for all 512 steps
//  - h staged with cp.async; inner loop interleaves 2 batches (8 acc chains)
//  - SPLIT grid barrier: arrive right after h-write, z tanh+store overlaps
//    barrier propagation, then spin-wait.
// ---------------------------------------------------------------------------
#define RECUR_SMEM ((16 * 1024 + 16 * 16 * 32) * 4)  /* 64KB h + 32KB partials */

__global__ void __launch_bounds__(512, 1) recur_k(const float* __restrict__ Wh,
                                                  const float* __restrict__ bh) {
    extern __shared__ float sm[];
    float* hs   = sm;              // [16][1024]
    float* part = sm + 16 * 1024;  // [16][16][32]  (k-slice, b, j)

    const int tid = threadIdx.x;
    const int w   = tid >> 5;            // warp id 0..15 -> k slice
    const int l   = tid & 31;            // lane -> j
    const int cb  = blockIdx.x;
    const int j0  = (cb & 31) << 5;      // 32 j per CTA
    const int b0  = (cb >> 5) << 4;      // 16 b per CTA
    const int j   = j0 + l;
    const int kw  = w << 6;              // k offset 0,64,...,960

    // Wh[j][kw..kw+63] -> 32 f32x2 registers (held for the whole kernel)
    unsigned long long wreg[32];
    {
        const float* src = &Wh[j * H_ + kw];
#pragma unroll
        for (int q = 0; q < 16; ++q) {
            float4 v = *(const float4*)&src[q << 2];
            wreg[2 * q]     = pk(v.x, v.y);
            wreg[2 * q + 1] = pk(v.z, v.w);
        }
    }

    // reduce-phase mapping: 512 threads = 16 b x 32 j, one output each
    const int rb = tid >> 5;             // 0..15 (batch row)
    const int gb = b0 + rb;
    const float bhj = bh[j];

    const unsigned hs_s = (unsigned)__cvta_generic_to_shared(hs);

    for (int m = 0; m < S_; ++m) {
        // ---- stage h_m slice (16 x 1024 floats) via cp.async ----
        {
            const float* hsrc = g_hbuf[m & 1] + (b0 << 10);
#pragma unroll
            for (int e = 0; e < 8; ++e) {
                int i = tid + (e << 9);           // 0..4095 float4 chunks
                asm volatile("cp.async.cg.shared.global [%0], [%1], 16;"
                             :: "r"(hs_s + (i << 4)), "l"(hsrc + (i << 2)));
            }
            asm volatile("cp.async.commit_group;");
        }
        // prefetch U[m] for this thread's output (overlaps the async fill)
        float u0 = 0.f;
        if (m <= S_ - 2) u0 = g_U[((long)m * 64 + gb) * H_ + j];
        asm volatile("cp.async.wait_group 0;" ::: "memory");
        __syncthreads();

        // ---- split-k partials: 8 pairs of batches, 8 acc chains ----
#pragma unroll 1
        for (int bp = 0; bp < 8; ++bp) {
            const float* hA = &hs[((bp << 1) << 10) + kw];
            const float* hB = &hs[(((bp << 1) + 1) << 10) + kw];
            unsigned long long a0 = 0ull, a1 = 0ull, a2 = 0ull, a3 = 0ull;
            unsigned long long c0 = 0ull, c1 = 0ull, c2 = 0ull, c3 = 0ull;
#pragma unroll
            for (int q = 0; q < 8; ++q) {
                ulonglong2 hA01 = *(const ulonglong2*)&hA[q << 3];
                ulonglong2 hA23 = *(const ulonglong2*)&hA[(q << 3) + 4];
                ulonglong2 hB01 = *(const ulonglong2*)&hB[q << 3];
                ulonglong2 hB23 = *(const ulonglong2*)&hB[(q << 3) + 4];
                ffma2(a0, hA01.x, wreg[4 * q]);
                ffma2(a1, hA01.y, wreg[4 * q + 1]);
                ffma2(a2, hA23.x, wreg[4 * q + 2]);
                ffma2(a3, hA23.y, wreg[4 * q + 3]);
                ffma2(c0, hB01.x, wreg[4 * q]);
                ffma2(c1, hB01.y, wreg[4 * q + 1]);
                ffma2(c2, hB23.x, wreg[4 * q + 2]);
                ffma2(c3, hB23.y, wreg[4 * q + 3]);
            }
            float2 fa0 = unpk(a0), fa1 = unpk(a1), fa2 = unpk(a2), fa3 = unpk(a3);
            float2 fc0 = unpk(c0), fc1 = unpk(c1), fc2 = unpk(c2), fc3 = unpk(c3);
            part[(w << 9) + ((bp << 1) << 5) + l] =
                ((fa0.x + fa0.y) + (fa1.x + fa1.y)) +
                ((fa2.x + fa2.y) + (fa3.x + fa3.y));
            part[(w << 9) + (((bp << 1) + 1) << 5) + l] =
                ((fc0.x + fc0.y) + (fc1.x + fc1.y)) +
                ((fc2.x + fc2.y) + (fc3.x + fc3.y));
        }
        __syncthreads();

        // ---- reduce 16 k-slices, bias, h write ----
        float av;
        {
            float s = 0.f;
#pragma unroll
            for (int ww = 0; ww < 16; ++ww)
                s += part[(ww << 9) + (rb << 5) + l];
            av = s + bhj;
            if (m <= S_ - 2) g_hbuf[(m + 1) & 1][gb * H_ + j] = tanhf(u0 + av);
        }

        if (m != S_ - 1) {
            // publish h, arrive on the grid barrier
            __syncthreads();
            if (tid == 0) {
                __threadfence();
                atomicAdd(&g_bar, 1u);
            }
            // overlap: z tanh + store while the barrier propagates
            if (m >= 1) g_Z[((long)gb * S_ + m) * H_ + j] = tanhf(av);
            // wait for all CTAs
            if (tid == 0) {
                unsigned target = (unsigned)(128 * (m + 1));
                unsigned v;
                do {
                    asm volatile("ld.acquire.gpu.global.u32 %0, [%1];"
                                 : "=r"(v) : "l"(&g_bar));
                } while (v < target);
            }
            __syncthreads();
        } else {
            g_Z[((long)gb * S_ + m) * H_ + j] = tanhf(av);
        }
    }
}

// ---------------------------------------------------------------------------
// Row softmax over O_=512 cols; warp per row, logits read from g_U (reused).
// ---------------------------------------------------------------------------
__global__ __launch_bounds__(256) void softmax_k(float* __restrict__ out) {
    int r = blockIdx.x * 8 + (threadIdx.x >> 5);
    int l = threadIdx.x & 31;
    const float* row = g_U + (long)r * O_;

    float4 v[4];
    float mx = -3.0e38f;
#pragma unroll
    for (int q = 0; q < 4; ++q) {
        v[q] = *(const float4*)&row[(l + (q << 5)) << 2];
        mx = fmaxf(mx, fmaxf(fmaxf(v[q].x, v[q].y), fmaxf(v[q].z, v[q].w)));
    }
#pragma unroll
    for (int o = 16; o; o >>= 1) mx = fmaxf(mx, __shfl_xor_sync(~0u, mx, o));

    float s = 0.f;
#pragma unroll
    for (int q = 0; q < 4; ++q) {
        v[q].x = expf(v[q].x - mx); v[q].y = expf(v[q].y - mx);
        v[q].z = expf(v[q].z - mx); v[q].w = expf(v[q].w - mx);
        s += (v[q].x + v[q].y) + (v[q].z + v[q].w);
    }
#pragma unroll
    for (int o = 16; o; o >>= 1) s += __shfl_xor_sync(~0u, s, o);
    float inv = 1.0f / s;

#pragma unroll
    for (int q = 0; q < 4; ++q) {
        float4 wv = make_float4(v[q].x * inv, v[q].y * inv, v[q].z * inv, v[q].w * inv);
        *(float4*)&out[(long)r * O_ + ((l + (q << 5)) << 2)] = wv;
    }
}

__global__ void copyht_k(float* __restrict__ dst) {
    int i = blockIdx.x * blockDim.x + threadIdx.x;
    if (i < B_ * H_) dst[i] = g_hbuf[1][i];
}

// ---------------------------------------------------------------------------
// Launch
// ---------------------------------------------------------------------------
extern "C" void kernel_launch(void* const* d_in, const int* in_sizes, int n_in,
                              void* d_out, int out_size) {
    const float* x  = (const float*)d_in[0];
    const float* h0 = (const float*)d_in[1];
    const float* Wi = (const float*)d_in[2];
    const float* bi = (const float*)d_in[3];
    const float* Wh = (const float*)d_in[4];
    const float* bh = (const float*)d_in[5];
    const float* W3 = (const float*)d_in[6];
    const float* b3 = (const float*)d_in[7];
    float* out = (float*)d_out;

    cudaFuncSetAttribute(recur_k, cudaFuncAttributeMaxDynamicSharedMemorySize,
                         RECUR_SMEM);

    // 1. h0 -> state, barrier reset
    init_k<<<(B_ * H_ + 255) / 256, 256>>>(h0);

    // 2. U[t][b][:] = x[b][t][:] @ Wi^T + bi   (t = 0..510)
    gemm_k<0><<<dim3(H_ / 64, S_ - 1), 256>>>(x, Wi, bi);

    // 3. Serial recurrence (persistent, 128 CTAs, 512 steps)
    recur_k<<<128, 512, RECUR_SMEM>>>(Wh, bh);

    // 4. logits = Z @ W3^T + b3   (writes g_U, reused as logits buffer)
    gemm_k<1><<<dim3(O_ / 64, (B_ * S_) / 64), 256>>>(nullptr, W3, b3);

    // 5. softmax -> d_out
    softmax_k<<<(B_ * S_) / 8, 256>>>(out);

    // 6. final hidden state appended after softmax output
    if (out_size >= B_ * S_ * O_ + B_ * H_) {
        copyht_k<<<(B_ * H_ + 255) / 256, 256>>>(out + (long)B_ * S_ * O_);
    }
}

// round 7
// speedup vs baseline: 1.1302x; 1.1302x over previous
#include <cuda_runtime.h>
#include <cuda_bf16.h>

#define B_ 64
#define S_ 512
#define I_ 512
#define H_ 1024
#define O_ 512

// ---------------------------------------------------------------------------
// Static device scratch (no allocations anywhere)
// ---------------------------------------------------------------------------
__device__ float g_U[(S_ - 1) * B_ * H_];   // U[t][b][j]; later reused as logits[r][o]
__device__ float g_Z[B_ * S_ * H_];         // Z[b][t][j]; t=0 slice stays .bss zero forever
__device__ float g_hbuf[2][B_ * H_];        // ping-pong hidden state
__device__ unsigned g_bar;                  // grid barrier counter

// ---------------------------------------------------------------------------
// f32x2 packed fp32 helpers (sm_100+): 2 fp32 MACs per issued instruction.
// ---------------------------------------------------------------------------
static __device__ __forceinline__ void ffma2(unsigned long long& d,
                                             unsigned long long a,
                                             unsigned long long b) {
    asm("fma.rn.f32x2 %0, %1, %2, %0;" : "+l"(d) : "l"(a), "l"(b));
}
static __device__ __forceinline__ unsigned long long pk(float x, float y) {
    unsigned long long r;
    asm("mov.b64 %0, {%1,%2};" : "=l"(r) : "f"(x), "f"(y));
    return r;
}
static __device__ __forceinline__ float2 unpk(unsigned long long v) {
    float2 r;
    asm("mov.b64 {%0,%1}, %2;" : "=f"(r.x), "=f"(r.y) : "l"(v));
    return r;
}

// ---------------------------------------------------------------------------
// Init: h0 -> g_hbuf[0], reset barrier counter
// ---------------------------------------------------------------------------
__global__ void init_k(const float* __restrict__ h0) {
    int i = blockIdx.x * blockDim.x + threadIdx.x;
    if (i < B_ * H_) g_hbuf[0][i] = h0[i];
    if (i == 0) g_bar = 0u;
}

// ---------------------------------------------------------------------------
// Tiled fp32 NT GEMM (exact R2 version — measured 48% fma, occ 59%).
// 64x64 tile, K-step 16, 256 threads, f32x2 accumulate.
//   MODE 0: U = x[:, t, :] @ Wi^T + bi       (y = t in 0..510, K=512,  N=1024)
//   MODE 1: logits = Z @ W3^T + b3           (y = row-tile,   K=1024, N=512)
// ---------------------------------------------------------------------------
template <int MODE>
__global__ __launch_bounds__(256) void gemm_k(const float* __restrict__ A,
                                              const float* __restrict__ W,
                                              const float* __restrict__ bias) {
    constexpr int K = (MODE == 0) ? I_ : H_;
    constexpr int N = (MODE == 0) ? H_ : O_;

    __shared__ float As[16][68];
    __shared__ float Ws[16][68];

    const int tid = threadIdx.x;
    const int n0 = blockIdx.x * 64;
    const int y  = blockIdx.y;
    const int lm = tid >> 2;        // 0..63 row for loads
    const int kq = (tid & 3) << 2;  // 0,4,8,12

    const int tx = tid & 15;        // 4-col group
    const int ty = tid >> 4;        // 4-row group

    unsigned long long acc[4][2];
#pragma unroll
    for (int i = 0; i < 4; ++i) { acc[i][0] = 0ull; acc[i][1] = 0ull; }

    for (int k0 = 0; k0 < K; k0 += 16) {
        float4 av;
        if (MODE == 0) {
            av = *(const float4*)&A[((lm << 9) + y) * I_ + k0 + kq];
        } else {
            av = *(const float4*)&g_Z[((y << 6) + lm) * H_ + k0 + kq];
        }
        float4 wv = *(const float4*)&W[(n0 + lm) * K + k0 + kq];
        As[kq + 0][lm] = av.x; As[kq + 1][lm] = av.y;
        As[kq + 2][lm] = av.z; As[kq + 3][lm] = av.w;
        Ws[kq + 0][lm] = wv.x; Ws[kq + 1][lm] = wv.y;
        Ws[kq + 2][lm] = wv.z; Ws[kq + 3][lm] = wv.w;
        __syncthreads();

#pragma unroll
        for (int kk = 0; kk < 16; ++kk) {
            ulonglong2 a2 = *(const ulonglong2*)&As[kk][ty << 2];
            float4 w4 = *(const float4*)&Ws[kk][tx << 2];
            unsigned long long w0 = pk(w4.x, w4.x);
            unsigned long long w1 = pk(w4.y, w4.y);
            unsigned long long w2 = pk(w4.z, w4.z);
            unsigned long long w3 = pk(w4.w, w4.w);
            ffma2(acc[0][0], a2.x, w0); ffma2(acc[0][1], a2.y, w0);
            ffma2(acc[1][0], a2.x, w1); ffma2(acc[1][1], a2.y, w1);
            ffma2(acc[2][0], a2.x, w2); ffma2(acc[2][1], a2.y, w2);
            ffma2(acc[3][0], a2.x, w3); ffma2(acc[3][1], a2.y, w3);
        }
        __syncthreads();
    }

    const float4 b4 = *(const float4*)&bias[n0 + (tx << 2)];
#pragma unroll
    for (int p = 0; p < 2; ++p) {
        float2 c0 = unpk(acc[0][p]);
        float2 c1 = unpk(acc[1][p]);
        float2 c2 = unpk(acc[2][p]);
        float2 c3 = unpk(acc[3][p]);
        int r_lo = (ty << 2) + (p << 1);
        float4 o0 = make_float4(c0.x + b4.x, c1.x + b4.y, c2.x + b4.z, c3.x + b4.w);
        float4 o1 = make_float4(c0.y + b4.x, c1.y + b4.y, c2.y + b4.z, c3.y + b4.w);
        long base0 = (long)((y << 6) + r_lo) * N + n0 + (tx << 2);
        *(float4*)&g_U[base0]     = o0;
        *(float4*)&g_U[base0 + N] = o1;
    }
}

// ---------------------------------------------------------------------------
// Persistent recurrence kernel v6:
//  - 512 threads (16 warps = 4/SMSP), 128 CTAs = 4 b-groups x 32 j-groups
//  - warp w owns k-slice [w*64, w*64+64); lane l owns j = j0 + l
//  - Wh[j][k-slice] in 32 f32x2 registers for all 512 steps
//  - TWO-PHASE cp.async staging: batches 8..15 fill while 0..7 compute
//  - split grid barrier: z tanh+store overlaps barrier propagation
// ---------------------------------------------------------------------------
#define RECUR_SMEM ((16 * 1024 + 16 * 16 * 32) * 4)  /* 64KB h + 32KB partials */

__global__ void __launch_bounds__(512, 1) recur_k(const float* __restrict__ Wh,
                                                  const float* __restrict__ bh) {
    extern __shared__ float sm[];
    float* hs   = sm;              // [16][1024]
    float* part = sm + 16 * 1024;  // [16][16][32]  (k-slice, b, j)

    const int tid = threadIdx.x;
    const int w   = tid >> 5;            // warp id 0..15 -> k slice
    const int l   = tid & 31;            // lane -> j
    const int cb  = blockIdx.x;
    const int j0  = (cb & 31) << 5;      // 32 j per CTA
    const int b0  = (cb >> 5) << 4;      // 16 b per CTA
    const int j   = j0 + l;
    const int kw  = w << 6;              // k offset 0,64,...,960

    // Wh[j][kw..kw+63] -> 32 f32x2 registers (held for the whole kernel)
    unsigned long long wreg[32];
    {
        const float* src = &Wh[j * H_ + kw];
#pragma unroll
        for (int q = 0; q < 16; ++q) {
            float4 v = *(const float4*)&src[q << 2];
            wreg[2 * q]     = pk(v.x, v.y);
            wreg[2 * q + 1] = pk(v.z, v.w);
        }
    }

    // reduce-phase mapping: 512 threads = 16 b x 32 j, one output each
    const int rb = tid >> 5;             // 0..15 (batch row)
    const int gb = b0 + rb;
    const float bhj = bh[j];

    const unsigned hs_s = (unsigned)__cvta_generic_to_shared(hs);

    for (int m = 0; m < S_; ++m) {
        const float* hsrc = g_hbuf[m & 1] + (b0 << 10);

        // ---- phase A: stage batches 0..7 (2048 float4) ----
#pragma unroll
        for (int e = 0; e < 4; ++e) {
            int i = tid + (e << 9);
            asm volatile("cp.async.cg.shared.global [%0], [%1], 16;"
                         :: "r"(hs_s + (i << 4)), "l"(hsrc + (i << 2)));
        }
        asm volatile("cp.async.commit_group;");
        // ---- phase B: stage batches 8..15 ----
#pragma unroll
        for (int e = 0; e < 4; ++e) {
            int i = 2048 + tid + (e << 9);
            asm volatile("cp.async.cg.shared.global [%0], [%1], 16;"
                         :: "r"(hs_s + (i << 4)), "l"(hsrc + (i << 2)));
        }
        asm volatile("cp.async.commit_group;");

        // prefetch U[m] for this thread's output (overlaps the async fill)
        float u0 = 0.f;
        if (m <= S_ - 2) u0 = g_U[((long)m * 64 + gb) * H_ + j];

        asm volatile("cp.async.wait_group 1;" ::: "memory");  // phase A ready
        __syncthreads();

        // ---- split-k partials, first 8 batches (B fills in the shadow) ----
#pragma unroll 1
        for (int bp = 0; bp < 8; ++bp) {
            const int half = (bp >> 2);          // 0: batches 0..7, 1: 8..15
            if (bp == 4) {                       // switch to second half
                asm volatile("cp.async.wait_group 0;" ::: "memory");
                __syncthreads();
            }
            const int bA = (bp << 1);
            const float* hA = &hs[(bA << 10) + kw];
            const float* hB = &hs[((bA + 1) << 10) + kw];
            unsigned long long a0 = 0ull, a1 = 0ull, a2 = 0ull, a3 = 0ull;
            unsigned long long c0 = 0ull, c1 = 0ull, c2 = 0ull, c3 = 0ull;
#pragma unroll
            for (int q = 0; q < 8; ++q) {
                ulonglong2 hA01 = *(const ulonglong2*)&hA[q << 3];
                ulonglong2 hA23 = *(const ulonglong2*)&hA[(q << 3) + 4];
                ulonglong2 hB01 = *(const ulonglong2*)&hB[q << 3];
                ulonglong2 hB23 = *(const ulonglong2*)&hB[(q << 3) + 4];
                ffma2(a0, hA01.x, wreg[4 * q]);
                ffma2(a1, hA01.y, wreg[4 * q + 1]);
                ffma2(a2, hA23.x, wreg[4 * q + 2]);
                ffma2(a3, hA23.y, wreg[4 * q + 3]);
                ffma2(c0, hB01.x, wreg[4 * q]);
                ffma2(c1, hB01.y, wreg[4 * q + 1]);
                ffma2(c2, hB23.x, wreg[4 * q + 2]);
                ffma2(c3, hB23.y, wreg[4 * q + 3]);
            }
            float2 fa0 = unpk(a0), fa1 = unpk(a1), fa2 = unpk(a2), fa3 = unpk(a3);
            float2 fc0 = unpk(c0), fc1 = unpk(c1), fc2 = unpk(c2), fc3 = unpk(c3);
            part[(w << 9) + (bA << 5) + l] =
                ((fa0.x + fa0.y) + (fa1.x + fa1.y)) +
                ((fa2.x + fa2.y) + (fa3.x + fa3.y));
            part[(w << 9) + ((bA + 1) << 5) + l] =
                ((fc0.x + fc0.y) + (fc1.x + fc1.y)) +
                ((fc2.x + fc2.y) + (fc3.x + fc3.y));
            (void)half;
        }
        __syncthreads();

        // ---- reduce 16 k-slices, bias, h write ----
        float av;
        {
            float s = 0.f;
#pragma unroll
            for (int ww = 0; ww < 16; ++ww)
                s += part[(ww << 9) + (rb << 5) + l];
            av = s + bhj;
            if (m <= S_ - 2) g_hbuf[(m + 1) & 1][gb * H_ + j] = tanhf(u0 + av);
        }

        if (m != S_ - 1) {
            // publish h, arrive on the grid barrier
            __syncthreads();
            if (tid == 0) {
                __threadfence();
                atomicAdd(&g_bar, 1u);
            }
            // overlap: z tanh + store while the barrier propagates
            if (m >= 1) g_Z[((long)gb * S_ + m) * H_ + j] = tanhf(av);
            // wait for all CTAs
            if (tid == 0) {
                unsigned target = (unsigned)(128 * (m + 1));
                unsigned v;
                do {
                    asm volatile("ld.acquire.gpu.global.u32 %0, [%1];"
                                 : "=r"(v) : "l"(&g_bar));
                } while (v < target);
            }
            __syncthreads();
        } else {
            g_Z[((long)gb * S_ + m) * H_ + j] = tanhf(av);
        }
    }
}

// ---------------------------------------------------------------------------
// Row softmax over O_=512 cols; warp per row, logits read from g_U (reused).
// ---------------------------------------------------------------------------
__global__ __launch_bounds__(256) void softmax_k(float* __restrict__ out) {
    int r = blockIdx.x * 8 + (threadIdx.x >> 5);
    int l = threadIdx.x & 31;
    const float* row = g_U + (long)r * O_;

    float4 v[4];
    float mx = -3.0e38f;
#pragma unroll
    for (int q = 0; q < 4; ++q) {
        v[q] = *(const float4*)&row[(l + (q << 5)) << 2];
        mx = fmaxf(mx, fmaxf(fmaxf(v[q].x, v[q].y), fmaxf(v[q].z, v[q].w)));
    }
#pragma unroll
    for (int o = 16; o; o >>= 1) mx = fmaxf(mx, __shfl_xor_sync(~0u, mx, o));

    float s = 0.f;
#pragma unroll
    for (int q = 0; q < 4; ++q) {
        v[q].x = expf(v[q].x - mx); v[q].y = expf(v[q].y - mx);
        v[q].z = expf(v[q].z - mx); v[q].w = expf(v[q].w - mx);
        s += (v[q].x + v[q].y) + (v[q].z + v[q].w);
    }
#pragma unroll
    for (int o = 16; o; o >>= 1) s += __shfl_xor_sync(~0u, s, o);
    float inv = 1.0f / s;

#pragma unroll
    for (int q = 0; q < 4; ++q) {
        float4 wv = make_float4(v[q].x * inv, v[q].y * inv, v[q].z * inv, v[q].w * inv);
        *(float4*)&out[(long)r * O_ + ((l + (q << 5)) << 2)] = wv;
    }
}

__global__ void copyht_k(float* __restrict__ dst) {
    int i = blockIdx.x * blockDim.x + threadIdx.x;
    if (i < B_ * H_) dst[i] = g_hbuf[1][i];
}

// ---------------------------------------------------------------------------
// Launch
// ---------------------------------------------------------------------------
extern "C" void kernel_launch(void* const* d_in, const int* in_sizes, int n_in,
                              void* d_out, int out_size) {
    const float* x  = (const float*)d_in[0];
    const float* h0 = (const float*)d_in[1];
    const float* Wi = (const float*)d_in[2];
    const float* bi = (const float*)d_in[3];
    const float* Wh = (const float*)d_in[4];
    const float* bh = (const float*)d_in[5];
    const float* W3 = (const float*)d_in[6];
    const float* b3 = (const float*)d_in[7];
    float* out = (float*)d_out;

    cudaFuncSetAttribute(recur_k, cudaFuncAttributeMaxDynamicSharedMemorySize,
                         RECUR_SMEM);

    // 1. h0 -> state, barrier reset
    init_k<<<(B_ * H_ + 255) / 256, 256>>>(h0);

    // 2. U[t][b][:] = x[b][t][:] @ Wi^T + bi   (t = 0..510)
    gemm_k<0><<<dim3(H_ / 64, S_ - 1), 256>>>(x, Wi, bi);

    // 3. Serial recurrence (persistent, 128 CTAs, 512 steps)
    recur_k<<<128, 512, RECUR_SMEM>>>(Wh, bh);

    // 4. logits = Z @ W3^T + b3   (writes g_U, reused as logits buffer)
    gemm_k<1><<<dim3(O_ / 64, (B_ * S_) / 64), 256>>>(nullptr, W3, b3);

    // 5. softmax -> d_out
    softmax_k<<<(B_ * S_) / 8, 256>>>(out);

    // 6. final hidden state appended after softmax output
    if (out_size >= B_ * S_ * O_ + B_ * H_) {
        copyht_k<<<(B_ * H_ + 255) / 256, 256>>>(out + (long)B_ * S_ * O_);
    }
}

// round 8
// speedup vs baseline: 1.3817x; 1.2225x over previous
#include <cuda_runtime.h>
#include <cuda_bf16.h>

#define B_ 64
#define S_ 512
#define I_ 512
#define H_ 1024
#define O_ 512

// ---------------------------------------------------------------------------
// Static device scratch (no allocations anywhere)
// ---------------------------------------------------------------------------
__device__ float g_U[(S_ - 1) * B_ * H_];   // U[t][b][j]; later reused as logits[r][o]
__device__ float g_Z[B_ * S_ * H_];         // Z[b][t][j]; t=0 slice stays .bss zero forever
__device__ float g_hbuf[2][B_ * H_];        // ping-pong hidden state
__device__ unsigned g_bar;                  // grid barrier counter

// ---------------------------------------------------------------------------
// f32x2 packed fp32 helpers (sm_100+): 2 fp32 MACs per issued instruction.
// ---------------------------------------------------------------------------
static __device__ __forceinline__ void ffma2(unsigned long long& d,
                                             unsigned long long a,
                                             unsigned long long b) {
    asm("fma.rn.f32x2 %0, %1, %2, %0;" : "+l"(d) : "l"(a), "l"(b));
}
static __device__ __forceinline__ unsigned long long pk(float x, float y) {
    unsigned long long r;
    asm("mov.b64 %0, {%1,%2};" : "=l"(r) : "f"(x), "f"(y));
    return r;
}
static __device__ __forceinline__ float2 unpk(unsigned long long v) {
    float2 r;
    asm("mov.b64 {%0,%1}, %2;" : "=f"(r.x), "=f"(r.y) : "l"(v));
    return r;
}

// ---------------------------------------------------------------------------
// Init: h0 -> g_hbuf[0], reset barrier counter
// ---------------------------------------------------------------------------
__global__ void init_k(const float* __restrict__ h0) {
    int i = blockIdx.x * blockDim.x + threadIdx.x;
    if (i < B_ * H_) g_hbuf[0][i] = h0[i];
    if (i == 0) g_bar = 0u;
}

// ---------------------------------------------------------------------------
// Tensor-core GEMM: C = A @ W^T + bias in split-bf16 (hi/lo), fp32 accum.
//   acc += Ahi*Whi + Ahi*Wlo + Alo*Whi   (lo*lo dropped, rel err ~2^-16)
// CTA: 64 rows x 64 cols, 256 threads = 8 warps (2m x 4n), warp tile 32x16.
// SMEM: per 16-k chunk, A/W hi+lo as 8x8 bf16 tiles, each tile contiguous
// 128B -> conflict-free ldmatrix.
//   MODE 0: U = x[:, t, :] @ Wi^T + bi   (y = t, rows = b, K=512,  N=1024)
//   MODE 1: logits = Z @ W3^T + b3       (rows = b*512+t,   K=1024, N=512)
// ---------------------------------------------------------------------------
static __device__ __forceinline__ void ldsm_x4(unsigned& r0, unsigned& r1,
                                               unsigned& r2, unsigned& r3,
                                               unsigned addr) {
    asm volatile("ldmatrix.sync.aligned.m8n8.x4.shared.b16 {%0,%1,%2,%3}, [%4];"
                 : "=r"(r0), "=r"(r1), "=r"(r2), "=r"(r3) : "r"(addr));
}
static __device__ __forceinline__ void ldsm_x2(unsigned& r0, unsigned& r1,
                                               unsigned addr) {
    asm volatile("ldmatrix.sync.aligned.m8n8.x2.shared.b16 {%0,%1}, [%2];"
                 : "=r"(r0), "=r"(r1) : "r"(addr));
}
static __device__ __forceinline__ void mma16816(float* c, const unsigned* a,
                                                const unsigned* b) {
    asm volatile("mma.sync.aligned.m16n8k16.row.col.f32.bf16.bf16.f32 "
                 "{%0,%1,%2,%3}, {%4,%5,%6,%7}, {%8,%9}, {%0,%1,%2,%3};"
                 : "+f"(c[0]), "+f"(c[1]), "+f"(c[2]), "+f"(c[3])
                 : "r"(a[0]), "r"(a[1]), "r"(a[2]), "r"(a[3]),
                   "r"(b[0]), "r"(b[1]));
}

// fp32x4 -> hi/lo bf16x2 pairs, stored at tile offset (8B each)
static __device__ __forceinline__ void cvt_store(float4 v,
                                                 __nv_bfloat16* hi,
                                                 __nv_bfloat16* lo, int off) {
    __nv_bfloat162 h01 = __float22bfloat162_rn(make_float2(v.x, v.y));
    __nv_bfloat162 h23 = __float22bfloat162_rn(make_float2(v.z, v.w));
    float2 l01f = make_float2(v.x - __bfloat162float(h01.x),
                              v.y - __bfloat162float(h01.y));
    float2 l23f = make_float2(v.z - __bfloat162float(h23.x),
                              v.w - __bfloat162float(h23.y));
    *(__nv_bfloat162*)(hi + off)     = h01;
    *(__nv_bfloat162*)(hi + off + 2) = h23;
    *(__nv_bfloat162*)(lo + off)     = __float22bfloat162_rn(l01f);
    *(__nv_bfloat162*)(lo + off + 2) = __float22bfloat162_rn(l23f);
}

template <int MODE>
__global__ __launch_bounds__(256) void gemm_k(const float* __restrict__ A,
                                              const float* __restrict__ W,
                                              const float* __restrict__ bias) {
    constexpr int K = (MODE == 0) ? I_ : H_;
    constexpr int N = (MODE == 0) ? H_ : O_;
    constexpr int NCHUNK = K / 16;

    __shared__ __align__(16) __nv_bfloat16 sAhi[1024];   // 64 rows x 16 k
    __shared__ __align__(16) __nv_bfloat16 sAlo[1024];
    __shared__ __align__(16) __nv_bfloat16 sWhi[1024];   // 64 n    x 16 k
    __shared__ __align__(16) __nv_bfloat16 sWlo[1024];

    const int tid  = threadIdx.x;
    const int lane = tid & 31;
    const int wid  = tid >> 5;
    const int wm   = wid & 1;        // m half (32 rows)
    const int wn   = wid >> 1;       // n quarter (16 cols)
    const int n0   = blockIdx.x * 64;
    const int y    = blockIdx.y;

    // staging: thread -> (row sm_, k quad kq); 8x8-tile offset in halves
    const int sm_ = tid >> 2;
    const int kq  = (tid & 3) << 2;
    const int soff = (((sm_ >> 3) << 1) + (kq >> 3)) * 64 + ((sm_ & 7) << 3) + (kq & 7);

    const float* gA = (MODE == 0)
        ? &A[(((long)sm_ << 9) + y) * I_ + kq]
        : &g_Z[(((long)y << 6) + sm_) * H_ + kq];
    const float* gW = &W[(long)(n0 + sm_) * K + kq];

    float acc[2][2][4];
#pragma unroll
    for (int i = 0; i < 2; ++i)
#pragma unroll
        for (int j = 0; j < 2; ++j)
#pragma unroll
            for (int q = 0; q < 4; ++q) acc[i][j][q] = 0.f;

    const unsigned bAhi = (unsigned)__cvta_generic_to_shared(sAhi);
    const unsigned bAlo = (unsigned)__cvta_generic_to_shared(sAlo);
    const unsigned bWhi = (unsigned)__cvta_generic_to_shared(sWhi);
    const unsigned bWlo = (unsigned)__cvta_generic_to_shared(sWlo);

    // ldmatrix lane addressing (byte offsets into tiled layout)
    const int g4   = lane >> 3;          // 0..3 (x4 matrix group)
    const int g2   = g4 & 1;             // 0..1 (x2 matrix group)
    const int rowi = (lane & 7) << 4;    // row-in-tile * 16B

    // prefetch chunk 0
    float4 vA = *(const float4*)gA;
    float4 vW = *(const float4*)gW;

    for (int c = 0; c < NCHUNK; ++c) {
        cvt_store(vA, sAhi, sAlo, soff);
        cvt_store(vW, sWhi, sWlo, soff);
        __syncthreads();

        if (c + 1 < NCHUNK) {
            vA = *(const float4*)(gA + (c + 1) * 16);
            vW = *(const float4*)(gW + (c + 1) * 16);
        }

        // load fragments
        unsigned ahi[2][4], alo[2][4], bhi[2][2], blo[2][2];
#pragma unroll
        for (int mf = 0; mf < 2; ++mf) {
            int mi = wm * 4 + mf * 2;
            unsigned ti = (unsigned)((mi + (g4 & 1)) * 2 + (g4 >> 1));
            unsigned off = ti * 128u + rowi;
            ldsm_x4(ahi[mf][0], ahi[mf][1], ahi[mf][2], ahi[mf][3], bAhi + off);
            ldsm_x4(alo[mf][0], alo[mf][1], alo[mf][2], alo[mf][3], bAlo + off);
        }
#pragma unroll
        for (int nf = 0; nf < 2; ++nf) {
            int ni = wn * 2 + nf;
            unsigned ti = (unsigned)(ni * 2 + g2);
            unsigned off = ti * 128u + rowi;
            ldsm_x2(bhi[nf][0], bhi[nf][1], bWhi + off);
            ldsm_x2(blo[nf][0], blo[nf][1], bWlo + off);
        }

        // 3-product split-bf16 MMA
#pragma unroll
        for (int mf = 0; mf < 2; ++mf)
#pragma unroll
            for (int nf = 0; nf < 2; ++nf) {
                mma16816(acc[mf][nf], ahi[mf], bhi[nf]);
                mma16816(acc[mf][nf], ahi[mf], blo[nf]);
                mma16816(acc[mf][nf], alo[mf], bhi[nf]);
            }
        __syncthreads();
    }

    // epilogue: bias + write fp32
#pragma unroll
    for (int nf = 0; nf < 2; ++nf) {
        int bcol = n0 + wn * 16 + nf * 8 + ((lane & 3) << 1);
        float2 bv = *(const float2*)&bias[bcol];
#pragma unroll
        for (int mf = 0; mf < 2; ++mf) {
            long r0 = (long)(y << 6) + wm * 32 + mf * 16 + (lane >> 2);
            float2 o0 = make_float2(acc[mf][nf][0] + bv.x, acc[mf][nf][1] + bv.y);
            float2 o1 = make_float2(acc[mf][nf][2] + bv.x, acc[mf][nf][3] + bv.y);
            *(float2*)&g_U[r0 * N + bcol]       = o0;
            *(float2*)&g_U[(r0 + 8) * N + bcol] = o1;
        }
    }
}

// ---------------------------------------------------------------------------
// Persistent recurrence kernel v6 (unchanged from R6 — measured win):
//  - 512 threads, 128 CTAs = 4 b-groups x 32 j-groups
//  - Wh register-resident; two-phase cp.async staging; split grid barrier
// ---------------------------------------------------------------------------
#define RECUR_SMEM ((16 * 1024 + 16 * 16 * 32) * 4)  /* 64KB h + 32KB partials */

__global__ void __launch_bounds__(512, 1) recur_k(const float* __restrict__ Wh,
                                                  const float* __restrict__ bh) {
    extern __shared__ float sm[];
    float* hs   = sm;              // [16][1024]
    float* part = sm + 16 * 1024;  // [16][16][32]  (k-slice, b, j)

    const int tid = threadIdx.x;
    const int w   = tid >> 5;            // warp id 0..15 -> k slice
    const int l   = tid & 31;            // lane -> j
    const int cb  = blockIdx.x;
    const int j0  = (cb & 31) << 5;      // 32 j per CTA
    const int b0  = (cb >> 5) << 4;      // 16 b per CTA
    const int j   = j0 + l;
    const int kw  = w << 6;              // k offset 0,64,...,960

    unsigned long long wreg[32];
    {
        const float* src = &Wh[j * H_ + kw];
#pragma unroll
        for (int q = 0; q < 16; ++q) {
            float4 v = *(const float4*)&src[q << 2];
            wreg[2 * q]     = pk(v.x, v.y);
            wreg[2 * q + 1] = pk(v.z, v.w);
        }
    }

    const int rb = tid >> 5;             // 0..15 (batch row)
    const int gb = b0 + rb;
    const float bhj = bh[j];

    const unsigned hs_s = (unsigned)__cvta_generic_to_shared(hs);

    for (int m = 0; m < S_; ++m) {
        const float* hsrc = g_hbuf[m & 1] + (b0 << 10);

#pragma unroll
        for (int e = 0; e < 4; ++e) {
            int i = tid + (e << 9);
            asm volatile("cp.async.cg.shared.global [%0], [%1], 16;"
                         :: "r"(hs_s + (i << 4)), "l"(hsrc + (i << 2)));
        }
        asm volatile("cp.async.commit_group;");
#pragma unroll
        for (int e = 0; e < 4; ++e) {
            int i = 2048 + tid + (e << 9);
            asm volatile("cp.async.cg.shared.global [%0], [%1], 16;"
                         :: "r"(hs_s + (i << 4)), "l"(hsrc + (i << 2)));
        }
        asm volatile("cp.async.commit_group;");

        float u0 = 0.f;
        if (m <= S_ - 2) u0 = g_U[((long)m * 64 + gb) * H_ + j];

        asm volatile("cp.async.wait_group 1;" ::: "memory");
        __syncthreads();

#pragma unroll 1
        for (int bp = 0; bp < 8; ++bp) {
            if (bp == 4) {
                asm volatile("cp.async.wait_group 0;" ::: "memory");
                __syncthreads();
            }
            const int bA = (bp << 1);
            const float* hA = &hs[(bA << 10) + kw];
            const float* hB = &hs[((bA + 1) << 10) + kw];
            unsigned long long a0 = 0ull, a1 = 0ull, a2 = 0ull, a3 = 0ull;
            unsigned long long c0 = 0ull, c1 = 0ull, c2 = 0ull, c3 = 0ull;
#pragma unroll
            for (int q = 0; q < 8; ++q) {
                ulonglong2 hA01 = *(const ulonglong2*)&hA[q << 3];
                ulonglong2 hA23 = *(const ulonglong2*)&hA[(q << 3) + 4];
                ulonglong2 hB01 = *(const ulonglong2*)&hB[q << 3];
                ulonglong2 hB23 = *(const ulonglong2*)&hB[(q << 3) + 4];
                ffma2(a0, hA01.x, wreg[4 * q]);
                ffma2(a1, hA01.y, wreg[4 * q + 1]);
                ffma2(a2, hA23.x, wreg[4 * q + 2]);
                ffma2(a3, hA23.y, wreg[4 * q + 3]);
                ffma2(c0, hB01.x, wreg[4 * q]);
                ffma2(c1, hB01.y, wreg[4 * q + 1]);
                ffma2(c2, hB23.x, wreg[4 * q + 2]);
                ffma2(c3, hB23.y, wreg[4 * q + 3]);
            }
            float2 fa0 = unpk(a0), fa1 = unpk(a1), fa2 = unpk(a2), fa3 = unpk(a3);
            float2 fc0 = unpk(c0), fc1 = unpk(c1), fc2 = unpk(c2), fc3 = unpk(c3);
            part[(w << 9) + (bA << 5) + l] =
                ((fa0.x + fa0.y) + (fa1.x + fa1.y)) +
                ((fa2.x + fa2.y) + (fa3.x + fa3.y));
            part[(w << 9) + ((bA + 1) << 5) + l] =
                ((fc0.x + fc0.y) + (fc1.x + fc1.y)) +
                ((fc2.x + fc2.y) + (fc3.x + fc3.y));
        }
        __syncthreads();

        float av;
        {
            float s = 0.f;
#pragma unroll
            for (int ww = 0; ww < 16; ++ww)
                s += part[(ww << 9) + (rb << 5) + l];
            av = s + bhj;
            if (m <= S_ - 2) g_hbuf[(m + 1) & 1][gb * H_ + j] = tanhf(u0 + av);
        }

        if (m != S_ - 1) {
            __syncthreads();
            if (tid == 0) {
                __threadfence();
                atomicAdd(&g_bar, 1u);
            }
            if (m >= 1) g_Z[((long)gb * S_ + m) * H_ + j] = tanhf(av);
            if (tid == 0) {
                unsigned target = (unsigned)(128 * (m + 1));
                unsigned v;
                do {
                    asm volatile("ld.acquire.gpu.global.u32 %0, [%1];"
                                 : "=r"(v) : "l"(&g_bar));
                } while (v < target);
            }
            __syncthreads();
        } else {
            g_Z[((long)gb * S_ + m) * H_ + j] = tanhf(av);
        }
    }
}

// ---------------------------------------------------------------------------
// Row softmax over O_=512 cols; warp per row, logits read from g_U (reused).
// ---------------------------------------------------------------------------
__global__ __launch_bounds__(256) void softmax_k(float* __restrict__ out) {
    int r = blockIdx.x * 8 + (threadIdx.x >> 5);
    int l = threadIdx.x & 31;
    const float* row = g_U + (long)r * O_;

    float4 v[4];
    float mx = -3.0e38f;
#pragma unroll
    for (int q = 0; q < 4; ++q) {
        v[q] = *(const float4*)&row[(l + (q << 5)) << 2];
        mx = fmaxf(mx, fmaxf(fmaxf(v[q].x, v[q].y), fmaxf(v[q].z, v[q].w)));
    }
#pragma unroll
    for (int o = 16; o; o >>= 1) mx = fmaxf(mx, __shfl_xor_sync(~0u, mx, o));

    float s = 0.f;
#pragma unroll
    for (int q = 0; q < 4; ++q) {
        v[q].x = expf(v[q].x - mx); v[q].y = expf(v[q].y - mx);
        v[q].z = expf(v[q].z - mx); v[q].w = expf(v[q].w - mx);
        s += (v[q].x + v[q].y) + (v[q].z + v[q].w);
    }
#pragma unroll
    for (int o = 16; o; o >>= 1) s += __shfl_xor_sync(~0u, s, o);
    float inv = 1.0f / s;

#pragma unroll
    for (int q = 0; q < 4; ++q) {
        float4 wv = make_float4(v[q].x * inv, v[q].y * inv, v[q].z * inv, v[q].w * inv);
        *(float4*)&out[(long)r * O_ + ((l + (q << 5)) << 2)] = wv;
    }
}

__global__ void copyht_k(float* __restrict__ dst) {
    int i = blockIdx.x * blockDim.x + threadIdx.x;
    if (i < B_ * H_) dst[i] = g_hbuf[1][i];
}

// ---------------------------------------------------------------------------
// Launch
// ---------------------------------------------------------------------------
extern "C" void kernel_launch(void* const* d_in, const int* in_sizes, int n_in,
                              void* d_out, int out_size) {
    const float* x  = (const float*)d_in[0];
    const float* h0 = (const float*)d_in[1];
    const float* Wi = (const float*)d_in[2];
    const float* bi = (const float*)d_in[3];
    const float* Wh = (const float*)d_in[4];
    const float* bh = (const float*)d_in[5];
    const float* W3 = (const float*)d_in[6];
    const float* b3 = (const float*)d_in[7];
    float* out = (float*)d_out;

    cudaFuncSetAttribute(recur_k, cudaFuncAttributeMaxDynamicSharedMemorySize,
                         RECUR_SMEM);

    // 1. h0 -> state, barrier reset
    init_k<<<(B_ * H_ + 255) / 256, 256>>>(h0);

    // 2. U[t][b][:] = x[b][t][:] @ Wi^T + bi   (t = 0..510)
    gemm_k<0><<<dim3(H_ / 64, S_ - 1), 256>>>(x, Wi, bi);

    // 3. Serial recurrence (persistent, 128 CTAs, 512 steps)
    recur_k<<<128, 512, RECUR_SMEM>>>(Wh, bh);

    // 4. logits = Z @ W3^T + b3   (writes g_U, reused as logits buffer)
    gemm_k<1><<<dim3(O_ / 64, (B_ * S_) / 64), 256>>>(nullptr, W3, b3);

    // 5. softmax -> d_out
    softmax_k<<<(B_ * S_) / 8, 256>>>(out);

    // 6. final hidden state appended after softmax output
    if (out_size >= B_ * S_ * O_ + B_ * H_) {
        copyht_k<<<(B_ * H_ + 255) / 256, 256>>>(out + (long)B_ * S_ * O_);
    }
}

// round 9
// speedup vs baseline: 2.1730x; 1.5728x over previous
#include <cuda_runtime.h>
#include <cuda_bf16.h>

#define B_ 64
#define S_ 512
#define I_ 512
#define H_ 1024
#define O_ 512

// ---------------------------------------------------------------------------
// Static device scratch (no allocations anywhere)
// ---------------------------------------------------------------------------
__device__ float g_U[(S_ - 1) * B_ * H_];    // U[t][b][j]; reused as logits later
__device__ float g_Z[B_ * S_ * H_];          // Z[b][t][j]; t=0 slice stays zero
__device__ float g_ht[B_ * H_];              // final hidden state (fp32)
__device__ __nv_bfloat16 g_hbf[2][2][B_ * H_]; // [buf][hi/lo] h in 8x8-tiled bf16
__device__ unsigned g_bar;                   // grid barrier counter

// tiled index for (b, j): tile (b>>3, j>>3), within (b&7, j&7)
#define HTILE_IDX(b, j) ((((b) >> 3) * 128 + ((j) >> 3)) * 64 + (((b) & 7) << 3) + ((j) & 7))

// ---------------------------------------------------------------------------
// MMA / ldmatrix helpers (bf16, fp32 accum) — proven in R7 gemm
// ---------------------------------------------------------------------------
static __device__ __forceinline__ void ldsm_x4(unsigned& r0, unsigned& r1,
                                               unsigned& r2, unsigned& r3,
                                               unsigned addr) {
    asm volatile("ldmatrix.sync.aligned.m8n8.x4.shared.b16 {%0,%1,%2,%3}, [%4];"
                 : "=r"(r0), "=r"(r1), "=r"(r2), "=r"(r3) : "r"(addr));
}
static __device__ __forceinline__ void ldsm_x2(unsigned& r0, unsigned& r1,
                                               unsigned addr) {
    asm volatile("ldmatrix.sync.aligned.m8n8.x2.shared.b16 {%0,%1}, [%2];"
                 : "=r"(r0), "=r"(r1) : "r"(addr));
}
static __device__ __forceinline__ void mma16816(float* c, const unsigned* a,
                                                const unsigned* b) {
    asm volatile("mma.sync.aligned.m16n8k16.row.col.f32.bf16.bf16.f32 "
                 "{%0,%1,%2,%3}, {%4,%5,%6,%7}, {%8,%9}, {%0,%1,%2,%3};"
                 : "+f"(c[0]), "+f"(c[1]), "+f"(c[2]), "+f"(c[3])
                 : "r"(a[0]), "r"(a[1]), "r"(a[2]), "r"(a[3]),
                   "r"(b[0]), "r"(b[1]));
}

// fp32x4 -> hi/lo bf16x2 pairs (gemm staging)
static __device__ __forceinline__ void cvt_store(float4 v,
                                                 __nv_bfloat16* hi,
                                                 __nv_bfloat16* lo, int off) {
    __nv_bfloat162 h01 = __float22bfloat162_rn(make_float2(v.x, v.y));
    __nv_bfloat162 h23 = __float22bfloat162_rn(make_float2(v.z, v.w));
    float2 l01f = make_float2(v.x - __bfloat162float(h01.x),
                              v.y - __bfloat162float(h01.y));
    float2 l23f = make_float2(v.z - __bfloat162float(h23.x),
                              v.w - __bfloat162float(h23.y));
    *(__nv_bfloat162*)(hi + off)     = h01;
    *(__nv_bfloat162*)(hi + off + 2) = h23;
    *(__nv_bfloat162*)(lo + off)     = __float22bfloat162_rn(l01f);
    *(__nv_bfloat162*)(lo + off + 2) = __float22bfloat162_rn(l23f);
}

// ---------------------------------------------------------------------------
// Init: h0 -> g_hbf[0] (tiled bf16 hi/lo), reset barrier
// ---------------------------------------------------------------------------
__global__ void init_k(const float* __restrict__ h0) {
    int i = blockIdx.x * blockDim.x + threadIdx.x;
    if (i < B_ * H_) {
        int b = i >> 10, j = i & 1023;
        float v = h0[i];
        __nv_bfloat16 hi = __float2bfloat16(v);
        __nv_bfloat16 lo = __float2bfloat16(v - __bfloat162float(hi));
        int idx = HTILE_IDX(b, j);
        g_hbf[0][0][idx] = hi;
        g_hbf[0][1][idx] = lo;
    }
    if (i == 0) g_bar = 0u;
}

// ---------------------------------------------------------------------------
// Tensor-core GEMM (unchanged from R7 — measured win).
//   MODE 0: U = x[:, t, :] @ Wi^T + bi   (y = t, rows = b, K=512,  N=1024)
//   MODE 1: logits = Z @ W3^T + b3       (rows = b*512+t,   K=1024, N=512)
// ---------------------------------------------------------------------------
template <int MODE>
__global__ __launch_bounds__(256) void gemm_k(const float* __restrict__ A,
                                              const float* __restrict__ W,
                                              const float* __restrict__ bias) {
    constexpr int K = (MODE == 0) ? I_ : H_;
    constexpr int N = (MODE == 0) ? H_ : O_;
    constexpr int NCHUNK = K / 16;

    __shared__ __align__(16) __nv_bfloat16 sAhi[1024];
    __shared__ __align__(16) __nv_bfloat16 sAlo[1024];
    __shared__ __align__(16) __nv_bfloat16 sWhi[1024];
    __shared__ __align__(16) __nv_bfloat16 sWlo[1024];

    const int tid  = threadIdx.x;
    const int lane = tid & 31;
    const int wid  = tid >> 5;
    const int wm   = wid & 1;
    const int wn   = wid >> 1;
    const int n0   = blockIdx.x * 64;
    const int y    = blockIdx.y;

    const int sm_ = tid >> 2;
    const int kq  = (tid & 3) << 2;
    const int soff = (((sm_ >> 3) << 1) + (kq >> 3)) * 64 + ((sm_ & 7) << 3) + (kq & 7);

    const float* gA = (MODE == 0)
        ? &A[(((long)sm_ << 9) + y) * I_ + kq]
        : &g_Z[(((long)y << 6) + sm_) * H_ + kq];
    const float* gW = &W[(long)(n0 + sm_) * K + kq];

    float acc[2][2][4];
#pragma unroll
    for (int i = 0; i < 2; ++i)
#pragma unroll
        for (int j = 0; j < 2; ++j)
#pragma unroll
            for (int q = 0; q < 4; ++q) acc[i][j][q] = 0.f;

    const unsigned bAhi = (unsigned)__cvta_generic_to_shared(sAhi);
    const unsigned bAlo = (unsigned)__cvta_generic_to_shared(sAlo);
    const unsigned bWhi = (unsigned)__cvta_generic_to_shared(sWhi);
    const unsigned bWlo = (unsigned)__cvta_generic_to_shared(sWlo);

    const int g4   = lane >> 3;
    const int g2   = g4 & 1;
    const int rowi = (lane & 7) << 4;

    float4 vA = *(const float4*)gA;
    float4 vW = *(const float4*)gW;

    for (int c = 0; c < NCHUNK; ++c) {
        cvt_store(vA, sAhi, sAlo, soff);
        cvt_store(vW, sWhi, sWlo, soff);
        __syncthreads();

        if (c + 1 < NCHUNK) {
            vA = *(const float4*)(gA + (c + 1) * 16);
            vW = *(const float4*)(gW + (c + 1) * 16);
        }

        unsigned ahi[2][4], alo[2][4], bhi[2][2], blo[2][2];
#pragma unroll
        for (int mf = 0; mf < 2; ++mf) {
            int mi = wm * 4 + mf * 2;
            unsigned ti = (unsigned)((mi + (g4 & 1)) * 2 + (g4 >> 1));
            unsigned off = ti * 128u + rowi;
            ldsm_x4(ahi[mf][0], ahi[mf][1], ahi[mf][2], ahi[mf][3], bAhi + off);
            ldsm_x4(alo[mf][0], alo[mf][1], alo[mf][2], alo[mf][3], bAlo + off);
        }
#pragma unroll
        for (int nf = 0; nf < 2; ++nf) {
            int ni = wn * 2 + nf;
            unsigned ti = (unsigned)(ni * 2 + g2);
            unsigned off = ti * 128u + rowi;
            ldsm_x2(bhi[nf][0], bhi[nf][1], bWhi + off);
            ldsm_x2(blo[nf][0], blo[nf][1], bWlo + off);
        }

#pragma unroll
        for (int mf = 0; mf < 2; ++mf)
#pragma unroll
            for (int nf = 0; nf < 2; ++nf) {
                mma16816(acc[mf][nf], ahi[mf], bhi[nf]);
                mma16816(acc[mf][nf], ahi[mf], blo[nf]);
                mma16816(acc[mf][nf], alo[mf], bhi[nf]);
            }
        __syncthreads();
    }

#pragma unroll
    for (int nf = 0; nf < 2; ++nf) {
        int bcol = n0 + wn * 16 + nf * 8 + ((lane & 3) << 1);
        float2 bv = *(const float2*)&bias[bcol];
#pragma unroll
        for (int mf = 0; mf < 2; ++mf) {
            long r0 = (long)(y << 6) + wm * 32 + mf * 16 + (lane >> 2);
            float2 o0 = make_float2(acc[mf][nf][0] + bv.x, acc[mf][nf][1] + bv.y);
            float2 o1 = make_float2(acc[mf][nf][2] + bv.x, acc[mf][nf][3] + bv.y);
            *(float2*)&g_U[r0 * N + bcol]       = o0;
            *(float2*)&g_U[(r0 + 8) * N + bcol] = o1;
        }
    }
}

// ---------------------------------------------------------------------------
// Persistent recurrence kernel v7 — TENSOR CORES.
// 128 CTAs = 4 b-groups (16 b) x 32 j-groups (32 j); 512 threads = 16 warps.
// warp w owns k-slice [w*64, w*64+64).
// Wh (32 j x 1024 k) split-bf16 converted once; B-fragments live in REGISTERS
// for all 512 steps (4 k-steps x 4 n-tiles x 2 regs x hi/lo = 64 regs).
// h kept in global as tiled bf16 hi/lo; staged via cp.async; ldmatrix A frags;
// 48 mma.m16n8k16 per warp per step; padded-SMEM split-k reduce; tanh +
// bf16 h-write fused; split grid barrier with z-store overlap.
// ---------------------------------------------------------------------------
#define PSTRIDE 34
#define RECUR_SMEM (16384 * 2 * 2 + 16 * 16 * PSTRIDE * 4)  /* 64KB h + 34KB part */

__global__ void __launch_bounds__(512, 1) recur_k(const float* __restrict__ Wh,
                                                  const float* __restrict__ bh) {
    extern __shared__ char smraw[];
    __nv_bfloat16* hsH = (__nv_bfloat16*)smraw;          // 16384 halves (32KB)
    __nv_bfloat16* hsL = hsH + 16384;                    // 16384 halves (32KB)
    float* part = (float*)(smraw + 65536);               // [16][16][PSTRIDE]

    const int tid = threadIdx.x;
    const int w   = tid >> 5;            // warp 0..15 -> k slice [w*64, +64)
    const int l   = tid & 31;
    const int cb  = blockIdx.x;
    const int j0  = (cb & 31) << 5;      // 32 j per CTA
    const int bg  = cb >> 5;             // b-group 0..3
    const int b0  = bg << 4;
    const int j   = j0 + l;

    const unsigned baseH = (unsigned)__cvta_generic_to_shared(hsH);
    const unsigned baseL = (unsigned)__cvta_generic_to_shared(hsL);

    // ---- setup: Wh -> split-bf16 B fragments in registers (two passes) ----
    unsigned Bhi[4][4][2], Blo[4][4][2];   // [k-step][n-tile][2]
    {
        __nv_bfloat16* wtmp = hsH;         // 32768 halves = 64KB temp
        const unsigned baseW = baseH;
#pragma unroll 1
        for (int pass = 0; pass < 2; ++pass) {
#pragma unroll 1
            for (int it = 0; it < 16; ++it) {
                int e  = tid + (it << 9);
                int jj = e >> 8;                    // 0..31
                int k  = (e & 255) << 2;            // 0..1020
                float4 f = *(const float4*)&Wh[(long)(j0 + jj) * H_ + k];
                __nv_bfloat162 p01, p23;
                if (pass == 0) {
                    p01 = __float22bfloat162_rn(make_float2(f.x, f.y));
                    p23 = __float22bfloat162_rn(make_float2(f.z, f.w));
                } else {
                    __nv_bfloat162 h01 = __float22bfloat162_rn(make_float2(f.x, f.y));
                    __nv_bfloat162 h23 = __float22bfloat162_rn(make_float2(f.z, f.w));
                    p01 = __float22bfloat162_rn(make_float2(
                        f.x - __bfloat162float(h01.x), f.y - __bfloat162float(h01.y)));
                    p23 = __float22bfloat162_rn(make_float2(
                        f.z - __bfloat162float(h23.x), f.w - __bfloat162float(h23.y)));
                }
                int off = ((jj >> 3) * 128 + (k >> 3)) * 64 + ((jj & 7) << 3) + (k & 7);
                *(__nv_bfloat162*)(wtmp + off)     = p01;
                *(__nv_bfloat162*)(wtmp + off + 2) = p23;
            }
            __syncthreads();
#pragma unroll
            for (int s = 0; s < 4; ++s) {
                int kt0 = (w << 3) + (s << 1);
#pragma unroll
                for (int nt = 0; nt < 4; ++nt) {
                    unsigned addr = baseW +
                        (unsigned)(((nt * 128 + kt0 + ((l >> 3) & 1)) << 7) + ((l & 7) << 4));
                    if (pass == 0) ldsm_x2(Bhi[s][nt][0], Bhi[s][nt][1], addr);
                    else           ldsm_x2(Blo[s][nt][0], Blo[s][nt][1], addr);
                }
            }
            __syncthreads();
        }
    }

    const int rb = tid >> 5;             // reduce-phase batch row 0..15
    const int gb = b0 + rb;
    const float bhj = bh[j];

    for (int m = 0; m < S_; ++m) {
        // ---- stage h (tiled bf16 hi/lo, 64KB) via cp.async ----
        {
            const __nv_bfloat16* srcH = g_hbf[m & 1][0] + (bg << 14);
            const __nv_bfloat16* srcL = g_hbf[m & 1][1] + (bg << 14);
#pragma unroll
            for (int e = 0; e < 4; ++e) {
                int i = tid + (e << 9);            // 0..2047 16B chunks
                asm volatile("cp.async.cg.shared.global [%0], [%1], 16;"
                             :: "r"(baseH + (i << 4)), "l"(srcH + (i << 3)));
                asm volatile("cp.async.cg.shared.global [%0], [%1], 16;"
                             :: "r"(baseL + (i << 4)), "l"(srcL + (i << 3)));
            }
            asm volatile("cp.async.commit_group;");
        }
        float u0 = 0.f;
        if (m <= S_ - 2) u0 = g_U[((long)m * 64 + gb) * H_ + j];
        asm volatile("cp.async.wait_group 0;" ::: "memory");
        __syncthreads();

        // ---- split-k MMA: 4 k-steps x (2 ldsm.x4 + 12 mma) ----
        float acc[4][4];
#pragma unroll
        for (int nt = 0; nt < 4; ++nt)
#pragma unroll
            for (int q = 0; q < 4; ++q) acc[nt][q] = 0.f;

#pragma unroll
        for (int s = 0; s < 4; ++s) {
            int jt0 = (w << 3) + (s << 1);
            unsigned off = (unsigned)(((((l >> 3) & 1) * 128 + jt0 + (l >> 4)) << 7)
                                      + ((l & 7) << 4));
            unsigned aH[4], aL[4];
            ldsm_x4(aH[0], aH[1], aH[2], aH[3], baseH + off);
            ldsm_x4(aL[0], aL[1], aL[2], aL[3], baseL + off);
#pragma unroll
            for (int nt = 0; nt < 4; ++nt) {
                mma16816(acc[nt], aH, Bhi[s][nt]);
                mma16816(acc[nt], aH, Blo[s][nt]);
                mma16816(acc[nt], aL, Bhi[s][nt]);
            }
        }

        // ---- store partials (padded stride -> conflict-free) ----
        {
            float* pw = part + w * (16 * PSTRIDE);
            int prow = l >> 2, pcol = (l & 3) << 1;
#pragma unroll
            for (int nt = 0; nt < 4; ++nt) {
                *(float2*)&pw[prow * PSTRIDE + nt * 8 + pcol] =
                    make_float2(acc[nt][0], acc[nt][1]);
                *(float2*)&pw[(prow + 8) * PSTRIDE + nt * 8 + pcol] =
                    make_float2(acc[nt][2], acc[nt][3]);
            }
        }
        __syncthreads();

        // ---- reduce 16 k-slices, bias, tanh, h write (bf16 hi/lo) ----
        float av;
        {
            float s = 0.f;
#pragma unroll
            for (int ww = 0; ww < 16; ++ww)
                s += part[ww * (16 * PSTRIDE) + rb * PSTRIDE + l];
            av = s + bhj;
            if (m <= S_ - 2) {
                float hv = tanhf(u0 + av);
                __nv_bfloat16 hi = __float2bfloat16(hv);
                __nv_bfloat16 lo = __float2bfloat16(hv - __bfloat162float(hi));
                int idx = HTILE_IDX(gb, j);
                g_hbf[(m + 1) & 1][0][idx] = hi;
                g_hbf[(m + 1) & 1][1][idx] = lo;
                if (m == S_ - 2) g_ht[gb * H_ + j] = hv;   // exact fp32 ht
            }
        }

        if (m != S_ - 1) {
            __syncthreads();
            if (tid == 0) {
                __threadfence();
                atomicAdd(&g_bar, 1u);
            }
            // overlap: z tanh + store while barrier propagates
            if (m >= 1) g_Z[((long)gb * S_ + m) * H_ + j] = tanhf(av);
            if (tid == 0) {
                unsigned target = (unsigned)(128 * (m + 1));
                unsigned v;
                do {
                    asm volatile("ld.acquire.gpu.global.u32 %0, [%1];"
                                 : "=r"(v) : "l"(&g_bar));
                } while (v < target);
            }
            __syncthreads();
        } else {
            g_Z[((long)gb * S_ + m) * H_ + j] = tanhf(av);
        }
    }
}

// ---------------------------------------------------------------------------
// Row softmax over O_=512 cols; warp per row, logits read from g_U (reused).
// ---------------------------------------------------------------------------
__global__ __launch_bounds__(256) void softmax_k(float* __restrict__ out) {
    int r = blockIdx.x * 8 + (threadIdx.x >> 5);
    int l = threadIdx.x & 31;
    const float* row = g_U + (long)r * O_;

    float4 v[4];
    float mx = -3.0e38f;
#pragma unroll
    for (int q = 0; q < 4; ++q) {
        v[q] = *(const float4*)&row[(l + (q << 5)) << 2];
        mx = fmaxf(mx, fmaxf(fmaxf(v[q].x, v[q].y), fmaxf(v[q].z, v[q].w)));
    }
#pragma unroll
    for (int o = 16; o; o >>= 1) mx = fmaxf(mx, __shfl_xor_sync(~0u, mx, o));

    float s = 0.f;
#pragma unroll
    for (int q = 0; q < 4; ++q) {
        v[q].x = expf(v[q].x - mx); v[q].y = expf(v[q].y - mx);
        v[q].z = expf(v[q].z - mx); v[q].w = expf(v[q].w - mx);
        s += (v[q].x + v[q].y) + (v[q].z + v[q].w);
    }
#pragma unroll
    for (int o = 16; o; o >>= 1) s += __shfl_xor_sync(~0u, s, o);
    float inv = 1.0f / s;

#pragma unroll
    for (int q = 0; q < 4; ++q) {
        float4 wv = make_float4(v[q].x * inv, v[q].y * inv, v[q].z * inv, v[q].w * inv);
        *(float4*)&out[(long)r * O_ + ((l + (q << 5)) << 2)] = wv;
    }
}

__global__ void copyht_k(float* __restrict__ dst) {
    int i = blockIdx.x * blockDim.x + threadIdx.x;
    if (i < B_ * H_) dst[i] = g_ht[i];
}

// ---------------------------------------------------------------------------
// Launch
// ---------------------------------------------------------------------------
extern "C" void kernel_launch(void* const* d_in, const int* in_sizes, int n_in,
                              void* d_out, int out_size) {
    const float* x  = (const float*)d_in[0];
    const float* h0 = (const float*)d_in[1];
    const float* Wi = (const float*)d_in[2];
    const float* bi = (const float*)d_in[3];
    const float* Wh = (const float*)d_in[4];
    const float* bh = (const float*)d_in[5];
    const float* W3 = (const float*)d_in[6];
    const float* b3 = (const float*)d_in[7];
    float* out = (float*)d_out;

    cudaFuncSetAttribute(recur_k, cudaFuncAttributeMaxDynamicSharedMemorySize,
                         RECUR_SMEM);

    // 1. h0 -> tiled bf16 state, barrier reset
    init_k<<<(B_ * H_ + 255) / 256, 256>>>(h0);

    // 2. U[t][b][:] = x[b][t][:] @ Wi^T + bi   (t = 0..510)
    gemm_k<0><<<dim3(H_ / 64, S_ - 1), 256>>>(x, Wi, bi);

    // 3. Serial recurrence (persistent, 128 CTAs, 512 steps, tensor cores)
    recur_k<<<128, 512, RECUR_SMEM>>>(Wh, bh);

    // 4. logits = Z @ W3^T + b3   (writes g_U, reused as logits buffer)
    gemm_k<1><<<dim3(O_ / 64, (B_ * S_) / 64), 256>>>(nullptr, W3, b3);

    // 5. softmax -> d_out
    softmax_k<<<(B_ * S_) / 8, 256>>>(out);

    // 6. final hidden state appended after softmax output
    if (out_size >= B_ * S_ * O_ + B_ * H_) {
        copyht_k<<<(B_ * H_ + 255) / 256, 256>>>(out + (long)B_ * S_ * O_);
    }
}

// round 12
// speedup vs baseline: 2.6311x; 1.2108x over previous
#include <cuda_runtime.h>
#include <cuda_bf16.h>

#define B_ 64
#define S_ 512
#define I_ 512
#define H_ 1024
#define O_ 512

// ---------------------------------------------------------------------------
// Static device scratch (no allocations anywhere).
// All bf16 operand arrays use the 8x8-tile-contiguous layout:
//   tile (r>>3, k>>3), 64 halves (128 B) per tile, row-major tiles.
// NOTE: these are ONLY referenced from device code (host code must never
// take their address — that yields the host shadow symbol, the R9/R10 bug).
// ---------------------------------------------------------------------------
__device__ float g_U[(S_ - 1) * B_ * H_];      // U[t][b][j]; reused as logits
__device__ float g_ht[B_ * H_];                // final hidden state (fp32)
__device__ __nv_bfloat16 g_hbf[2][2][B_ * H_]; // [buf][hi/lo] h tiled bf16
__device__ __nv_bfloat16 g_xhi[B_ * S_ * I_];  // x tiled per t: ((t*8+bt)*64+kt)
__device__ __nv_bfloat16 g_xlo[B_ * S_ * I_];
__device__ __nv_bfloat16 g_zhi[B_ * S_ * H_];  // Z rows r=b*512+t: ((r>>3)*128+kt)
__device__ __nv_bfloat16 g_zlo[B_ * S_ * H_];  // t=0 rows never written -> zero
__device__ __nv_bfloat16 g_wihi[H_ * I_];      // Wi tiled ((n>>3)*64+kt)
__device__ __nv_bfloat16 g_wilo[H_ * I_];
__device__ __nv_bfloat16 g_w3hi[O_ * H_];      // W3 tiled ((n>>3)*128+kt)
__device__ __nv_bfloat16 g_w3lo[O_ * H_];
__device__ unsigned g_bar;                     // grid barrier counter

#define HTILE_IDX(b, j) ((((b) >> 3) * 128 + ((j) >> 3)) * 64 + (((b) & 7) << 3) + ((j) & 7))

// ---------------------------------------------------------------------------
// MMA / ldmatrix helpers (bf16, fp32 accum)
// ---------------------------------------------------------------------------
static __device__ __forceinline__ void ldsm_x2(unsigned& r0, unsigned& r1,
                                               unsigned addr) {
    asm volatile("ldmatrix.sync.aligned.m8n8.x2.shared.b16 {%0,%1}, [%2];"
                 : "=r"(r0), "=r"(r1) : "r"(addr));
}
static __device__ __forceinline__ void ldsm_x4(unsigned& r0, unsigned& r1,
                                               unsigned& r2, unsigned& r3,
                                               unsigned addr) {
    asm volatile("ldmatrix.sync.aligned.m8n8.x4.shared.b16 {%0,%1,%2,%3}, [%4];"
                 : "=r"(r0), "=r"(r1), "=r"(r2), "=r"(r3) : "r"(addr));
}
static __device__ __forceinline__ void mma16816(float* c, const unsigned* a,
                                                const unsigned* b) {
    asm volatile("mma.sync.aligned.m16n8k16.row.col.f32.bf16.bf16.f32 "
                 "{%0,%1,%2,%3}, {%4,%5,%6,%7}, {%8,%9}, {%0,%1,%2,%3};"
                 : "+f"(c[0]), "+f"(c[1]), "+f"(c[2]), "+f"(c[3])
                 : "r"(a[0]), "r"(a[1]), "r"(a[2]), "r"(a[3]),
                   "r"(b[0]), "r"(b[1]));
}
// L1-bypass 32-bit global load (h ping-pong is rewritten by other SMs)
static __device__ __forceinline__ unsigned ldcg(const void* p) {
    unsigned v;
    asm volatile("ld.global.cg.b32 %0, [%1];" : "=r"(v) : "l"(p));
    return v;
}

// fp32x4 -> hi/lo bf16x2 pairs written to (tiled) destinations
static __device__ __forceinline__ void cvt_pair(float4 v, __nv_bfloat16* hi,
                                                __nv_bfloat16* lo, long off) {
    __nv_bfloat162 h01 = __float22bfloat162_rn(make_float2(v.x, v.y));
    __nv_bfloat162 h23 = __float22bfloat162_rn(make_float2(v.z, v.w));
    float2 l01f = make_float2(v.x - __bfloat162float(h01.x),
                              v.y - __bfloat162float(h01.y));
    float2 l23f = make_float2(v.z - __bfloat162float(h23.x),
                              v.w - __bfloat162float(h23.y));
    *(__nv_bfloat162*)(hi + off)     = h01;
    *(__nv_bfloat162*)(hi + off + 2) = h23;
    *(__nv_bfloat162*)(lo + off)     = __float22bfloat162_rn(l01f);
    *(__nv_bfloat162*)(lo + off + 2) = __float22bfloat162_rn(l23f);
}

// ---------------------------------------------------------------------------
// Init + conversion kernels
// ---------------------------------------------------------------------------
__global__ void init_k(const float* __restrict__ h0) {
    int i = blockIdx.x * blockDim.x + threadIdx.x;
    if (i < B_ * H_) {
        int b = i >> 10, j = i & 1023;
        float v = h0[i];
        __nv_bfloat16 hi = __float2bfloat16(v);
        __nv_bfloat16 lo = __float2bfloat16(v - __bfloat162float(hi));
        int idx = HTILE_IDX(b, j);
        g_hbf[0][0][idx] = hi;
        g_hbf[0][1][idx] = lo;
    }
    if (i == 0) g_bar = 0u;
}

// x[b][t][k] -> per-t tiled: tile (t*8 + b>>3, k>>3)
__global__ void cvt_x_k(const float* __restrict__ x) {
    long i4 = (long)blockIdx.x * blockDim.x + threadIdx.x;
    if (i4 >= (long)B_ * S_ * I_ / 4) return;
    long e = i4 << 2;
    int b = (int)(e >> 18);
    int rem = (int)(e & 262143);
    int t = rem >> 9;
    int k = rem & 511;
    float4 v = *(const float4*)&x[e];
    long off = ((long)((t << 3) + (b >> 3)) * 64 + (k >> 3)) * 64
             + ((b & 7) << 3) + (k & 7);
    cvt_pair(v, g_xhi, g_xlo, off);
}

// W[n][k] (NR x NC) -> tiled: tile (n>>3, k>>3), NC/8 k-tiles per n-tile row
// WHICH: 0 -> (g_wihi, g_wilo), 1 -> (g_w3hi, g_w3lo)   [device-side select]
template <int NR, int NC, int WHICH>
__global__ void cvt_w_k(const float* __restrict__ W) {
    __nv_bfloat16* hi = (WHICH == 0) ? g_wihi : g_w3hi;
    __nv_bfloat16* lo = (WHICH == 0) ? g_wilo : g_w3lo;
    int i4 = blockIdx.x * blockDim.x + threadIdx.x;
    if (i4 >= NR * NC / 4) return;
    int e = i4 << 2;
    int n = e / NC, k = e % NC;
    float4 v = *(const float4*)&W[e];
    long off = ((long)(n >> 3) * (NC / 8) + (k >> 3)) * 64 + ((n & 7) << 3) + (k & 7);
    cvt_pair(v, hi, lo, off);
}

// ---------------------------------------------------------------------------
// Pure-bf16 tensor GEMM: operands pre-converted + pre-tiled in global,
// selected INSIDE device code by MODE (never passed from host).
// 64x64 CTA tile, 256 thr = 8 warps (2m x 4n), double-buffered cp.async
// (wait_group + __syncthreads = the SAFE visibility pattern).
//   MODE 0: U = x_t @ Wi^T + bi   (A = g_x*, W = g_wi*, K=512,  N=1024)
//   MODE 1: logits = Z @ W3^T+b3  (A = g_z*, W = g_w3*, K=1024, N=512)
// ---------------------------------------------------------------------------
template <int MODE>
__global__ __launch_bounds__(256) void gemm_bf(const float* __restrict__ bias) {
    constexpr int K = (MODE == 0) ? I_ : H_;
    constexpr int N = (MODE == 0) ? H_ : O_;
    constexpr int NCHUNK = K / 16;
    constexpr int KT = K / 8;

    const __nv_bfloat16* Ahi = (MODE == 0) ? g_xhi : g_zhi;
    const __nv_bfloat16* Alo = (MODE == 0) ? g_xlo : g_zlo;
    const __nv_bfloat16* Whi = (MODE == 0) ? g_wihi : g_w3hi;
    const __nv_bfloat16* Wlo = (MODE == 0) ? g_wilo : g_w3lo;

    __shared__ __align__(16) __nv_bfloat16 sbuf[2][4096];

    const int tid  = threadIdx.x;
    const int lane = tid & 31;
    const int wid  = tid >> 5;
    const int wm   = wid & 1;
    const int wn   = wid >> 1;
    const int n0   = blockIdx.x * 64;
    const int y    = blockIdx.y;

    const unsigned sbase = (unsigned)__cvta_generic_to_shared(&sbuf[0][0]);

    auto stage = [&](int c, int bufp) {
#pragma unroll
        for (int e = 0; e < 2; ++e) {
            int ci = tid + (e << 8);
            int a  = ci >> 7;                 // 0 Ahi,1 Alo,2 Whi,3 Wlo
            int tl = (ci & 127) >> 3;         // 0..15: bt*2+ktl
            int bt = tl >> 1, ktl = tl & 1;
            int kt = (c << 1) + ktl;
            int inner = (ci & 7) << 4;
            long tileIdx = (a < 2) ? ((long)((y << 3) + bt) * KT + kt)
                                   : ((long)((n0 >> 3) + bt) * KT + kt);
            const __nv_bfloat16* src =
                (a == 0 ? Ahi : a == 1 ? Alo : a == 2 ? Whi : Wlo);
            const char* gsrc = (const char*)src + tileIdx * 128 + inner;
            unsigned dst = sbase + (unsigned)(bufp * 8192 + a * 2048 + tl * 128 + inner);
            asm volatile("cp.async.cg.shared.global [%0], [%1], 16;"
                         :: "r"(dst), "l"(gsrc));
        }
    };

    float acc[2][2][4];
#pragma unroll
    for (int i = 0; i < 2; ++i)
#pragma unroll
        for (int j = 0; j < 2; ++j)
#pragma unroll
            for (int q = 0; q < 4; ++q) acc[i][j][q] = 0.f;

    const int g4   = lane >> 3;
    const int g2   = g4 & 1;
    const int rowi = (lane & 7) << 4;

    stage(0, 0);
    asm volatile("cp.async.commit_group;");

    for (int c = 0; c < NCHUNK; ++c) {
        const int cur = c & 1;
        if (c + 1 < NCHUNK) {
            stage(c + 1, cur ^ 1);
            asm volatile("cp.async.commit_group;");
            asm volatile("cp.async.wait_group 1;" ::: "memory");
        } else {
            asm volatile("cp.async.wait_group 0;" ::: "memory");
        }
        __syncthreads();

        const unsigned bA0 = sbase + (unsigned)(cur * 8192);
        const unsigned bA1 = bA0 + 2048;
        const unsigned bW0 = bA0 + 4096;
        const unsigned bW1 = bA0 + 6144;

        unsigned ahi[2][4], alo[2][4], bhi[2][2], blo[2][2];
#pragma unroll
        for (int mf = 0; mf < 2; ++mf) {
            int mi = wm * 4 + mf * 2;
            unsigned ti  = (unsigned)((mi + (g4 & 1)) * 2 + (g4 >> 1));
            unsigned off = ti * 128u + rowi;
            ldsm_x4(ahi[mf][0], ahi[mf][1], ahi[mf][2], ahi[mf][3], bA0 + off);
            ldsm_x4(alo[mf][0], alo[mf][1], alo[mf][2], alo[mf][3], bA1 + off);
        }
#pragma unroll
        for (int nf = 0; nf < 2; ++nf) {
            int ni = wn * 2 + nf;
            unsigned ti  = (unsigned)(ni * 2 + g2);
            unsigned off = ti * 128u + rowi;
            ldsm_x2(bhi[nf][0], bhi[nf][1], bW0 + off);
            ldsm_x2(blo[nf][0], blo[nf][1], bW1 + off);
        }

#pragma unroll
        for (int mf = 0; mf < 2; ++mf)
#pragma unroll
            for (int nf = 0; nf < 2; ++nf) {
                mma16816(acc[mf][nf], ahi[mf], bhi[nf]);
                mma16816(acc[mf][nf], ahi[mf], blo[nf]);
                mma16816(acc[mf][nf], alo[mf], bhi[nf]);
            }
        __syncthreads();
    }

#pragma unroll
    for (int nf = 0; nf < 2; ++nf) {
        int bcol = n0 + wn * 16 + nf * 8 + ((lane & 3) << 1);
        float2 bv = *(const float2*)&bias[bcol];
#pragma unroll
        for (int mf = 0; mf < 2; ++mf) {
            long r0 = (long)(y << 6) + wm * 32 + mf * 16 + (lane >> 2);
            float2 o0 = make_float2(acc[mf][nf][0] + bv.x, acc[mf][nf][1] + bv.y);
            float2 o1 = make_float2(acc[mf][nf][2] + bv.x, acc[mf][nf][3] + bv.y);
            *(float2*)&g_U[r0 * N + bcol]       = o0;
            *(float2*)&g_U[(r0 + 8) * N + bcol] = o1;
        }
    }
}

// ---------------------------------------------------------------------------
// Persistent recurrence kernel v9 — tensor cores, NO h staging:
// A-fragments loaded directly from tiled global h via coalesced ld.global.cg
// (ldmatrix-by-LDG emulation: lane l reads tile bytes (l>>2)*16+(l&3)*4).
// Wh B-fragments in registers for all 512 steps.
// ---------------------------------------------------------------------------
#define PSTRIDE 34
#define RECUR_SMEM (16384 * 2 * 2 + 16 * 16 * PSTRIDE * 4)

__global__ void __launch_bounds__(512, 1) recur_k(const float* __restrict__ Wh,
                                                  const float* __restrict__ bh) {
    extern __shared__ char smraw[];
    __nv_bfloat16* hsH = (__nv_bfloat16*)smraw;          // setup temp only
    float* part = (float*)(smraw + 65536);               // [16][16][PSTRIDE]

    const int tid = threadIdx.x;
    const int w   = tid >> 5;            // warp 0..15 -> k slice [w*64, +64)
    const int l   = tid & 31;
    const int cb  = blockIdx.x;
    const int j0  = (cb & 31) << 5;
    const int bg  = cb >> 5;
    const int b0  = bg << 4;
    const int j   = j0 + l;

    const unsigned baseW = (unsigned)__cvta_generic_to_shared(hsH);

    // ---- setup: Wh -> split-bf16 B fragments in registers (two passes) ----
    unsigned Bhi[4][4][2], Blo[4][4][2];
    {
        __nv_bfloat16* wtmp = hsH;
#pragma unroll 1
        for (int pass = 0; pass < 2; ++pass) {
#pragma unroll 1
            for (int it = 0; it < 16; ++it) {
                int e  = tid + (it << 9);
                int jj = e >> 8;
                int k  = (e & 255) << 2;
                float4 f = *(const float4*)&Wh[(long)(j0 + jj) * H_ + k];
                __nv_bfloat162 p01, p23;
                if (pass == 0) {
                    p01 = __float22bfloat162_rn(make_float2(f.x, f.y));
                    p23 = __float22bfloat162_rn(make_float2(f.z, f.w));
                } else {
                    __nv_bfloat162 h01 = __float22bfloat162_rn(make_float2(f.x, f.y));
                    __nv_bfloat162 h23 = __float22bfloat162_rn(make_float2(f.z, f.w));
                    p01 = __float22bfloat162_rn(make_float2(
                        f.x - __bfloat162float(h01.x), f.y - __bfloat162float(h01.y)));
                    p23 = __float22bfloat162_rn(make_float2(
                        f.z - __bfloat162float(h23.x), f.w - __bfloat162float(h23.y)));
                }
                int off = ((jj >> 3) * 128 + (k >> 3)) * 64 + ((jj & 7) << 3) + (k & 7);
                *(__nv_bfloat162*)(wtmp + off)     = p01;
                *(__nv_bfloat162*)(wtmp + off + 2) = p23;
            }
            __syncthreads();
#pragma unroll
            for (int s = 0; s < 4; ++s) {
                int kt0 = (w << 3) + (s << 1);
#pragma unroll
                for (int nt = 0; nt < 4; ++nt) {
                    unsigned addr = baseW +
                        (unsigned)(((nt * 128 + kt0 + ((l >> 3) & 1)) << 7) + ((l & 7) << 4));
                    if (pass == 0) ldsm_x2(Bhi[s][nt][0], Bhi[s][nt][1], addr);
                    else           ldsm_x2(Blo[s][nt][0], Blo[s][nt][1], addr);
                }
            }
            __syncthreads();
        }
    }

    const int rb = tid >> 5;
    const int gb = b0 + rb;
    const float bhj = bh[j];
    const int inner = ((l >> 2) << 4) + ((l & 3) << 2);   // frag byte in tile

    for (int m = 0; m < S_; ++m) {
        const char* hH = (const char*)(g_hbf[m & 1][0] + (bg << 14));
        const char* hL = (const char*)(g_hbf[m & 1][1] + (bg << 14));

        // fragment loader: k-step s -> tiles (bt, kt), (bt, kt+1), kt = w*8+2s
        auto loadfrag = [&](int s, unsigned* aH, unsigned* aL) {
            int kt = (w << 3) + (s << 1);
            int o00 = (kt << 7) + inner;      // bt0, kt
            int o10 = o00 + 16384;            // bt1, kt   (+128 tiles)
            aH[0] = ldcg(hH + o00); aH[1] = ldcg(hH + o10);
            aH[2] = ldcg(hH + o00 + 128); aH[3] = ldcg(hH + o10 + 128);
            aL[0] = ldcg(hL + o00); aL[1] = ldcg(hL + o10);
            aL[2] = ldcg(hL + o00 + 128); aL[3] = ldcg(hL + o10 + 128);
        };

        float u0 = 0.f;
        if (m <= S_ - 2) u0 = g_U[((long)m * 64 + gb) * H_ + j];

        float acc[4][4];
#pragma unroll
        for (int nt = 0; nt < 4; ++nt)
#pragma unroll
            for (int q = 0; q < 4; ++q) acc[nt][q] = 0.f;

        unsigned aH[2][4], aL[2][4];
        loadfrag(0, aH[0], aL[0]);
#pragma unroll
        for (int s = 0; s < 4; ++s) {
            const int cur = s & 1;
            if (s < 3) loadfrag(s + 1, aH[cur ^ 1], aL[cur ^ 1]);
#pragma unroll
            for (int nt = 0; nt < 4; ++nt) {
                mma16816(acc[nt], aH[cur], Bhi[s][nt]);
                mma16816(acc[nt], aH[cur], Blo[s][nt]);
                mma16816(acc[nt], aL[cur], Bhi[s][nt]);
            }
        }

        // ---- store partials (padded stride -> conflict-free) ----
        {
            float* pw = part + w * (16 * PSTRIDE);
            int prow = l >> 2, pcol = (l & 3) << 1;
#pragma unroll
            for (int nt = 0; nt < 4; ++nt) {
                *(float2*)&pw[prow * PSTRIDE + nt * 8 + pcol] =
                    make_float2(acc[nt][0], acc[nt][1]);
                *(float2*)&pw[(prow + 8) * PSTRIDE + nt * 8 + pcol] =
                    make_float2(acc[nt][2], acc[nt][3]);
            }
        }
        __syncthreads();

        // ---- reduce 16 k-slices, bias, tanh, h write (bf16 hi/lo) ----
        float av;
        {
            float s = 0.f;
#pragma unroll
            for (int ww = 0; ww < 16; ++ww)
                s += part[ww * (16 * PSTRIDE) + rb * PSTRIDE + l];
            av = s + bhj;
            if (m <= S_ - 2) {
                float hv = tanhf(u0 + av);
                __nv_bfloat16 hi = __float2bfloat16(hv);
                __nv_bfloat16 lo = __float2bfloat16(hv - __bfloat162float(hi));
                int idx = HTILE_IDX(gb, j);
                g_hbf[(m + 1) & 1][0][idx] = hi;
                g_hbf[(m + 1) & 1][1][idx] = lo;
                if (m == S_ - 2) g_ht[gb * H_ + j] = hv;
            }
        }

        // z write target (tiled bf16, rows r = b*512 + t)
        const int zr = (gb << 9) + m;
        const long zt = ((long)(zr >> 3) * 128 + (j >> 3)) * 64
                      + ((zr & 7) << 3) + (j & 7);

        if (m != S_ - 1) {
            __syncthreads();
            if (tid == 0) {
                __threadfence();
                atomicAdd(&g_bar, 1u);
            }
            // overlap: z tanh + bf16 store while barrier propagates
            if (m >= 1) {
                float zv = tanhf(av);
                __nv_bfloat16 zh = __float2bfloat16(zv);
                g_zhi[zt] = zh;
                g_zlo[zt] = __float2bfloat16(zv - __bfloat162float(zh));
            }
            if (tid == 0) {
                unsigned target = (unsigned)(128 * (m + 1));
                unsigned v;
                do {
                    asm volatile("ld.acquire.gpu.global.u32 %0, [%1];"
                                 : "=r"(v) : "l"(&g_bar));
                } while (v < target);
            }
            __syncthreads();
        } else {
            float zv = tanhf(av);
            __nv_bfloat16 zh = __float2bfloat16(zv);
            g_zhi[zt] = zh;
            g_zlo[zt] = __float2bfloat16(zv - __bfloat162float(zh));
        }
    }
}

// ---------------------------------------------------------------------------
// Row softmax over O_=512 cols; warp per row, logits read from g_U (reused).
// ---------------------------------------------------------------------------
__global__ __launch_bounds__(256) void softmax_k(float* __restrict__ out) {
    int r = blockIdx.x * 8 + (threadIdx.x >> 5);
    int l = threadIdx.x & 31;
    const float* row = g_U + (long)r * O_;

    float4 v[4];
    float mx = -3.0e38f;
#pragma unroll
    for (int q = 0; q < 4; ++q) {
        v[q] = *(const float4*)&row[(l + (q << 5)) << 2];
        mx = fmaxf(mx, fmaxf(fmaxf(v[q].x, v[q].y), fmaxf(v[q].z, v[q].w)));
    }
#pragma unroll
    for (int o = 16; o; o >>= 1) mx = fmaxf(mx, __shfl_xor_sync(~0u, mx, o));

    float s = 0.f;
#pragma unroll
    for (int q = 0; q < 4; ++q) {
        v[q].x = expf(v[q].x - mx); v[q].y = expf(v[q].y - mx);
        v[q].z = expf(v[q].z - mx); v[q].w = expf(v[q].w - mx);
        s += (v[q].x + v[q].y) + (v[q].z + v[q].w);
    }
#pragma unroll
    for (int o = 16; o; o >>= 1) s += __shfl_xor_sync(~0u, s, o);
    float inv = 1.0f / s;

#pragma unroll
    for (int q = 0; q < 4; ++q) {
        float4 wv = make_float4(v[q].x * inv, v[q].y * inv, v[q].z * inv, v[q].w * inv);
        *(float4*)&out[(long)r * O_ + ((l + (q << 5)) << 2)] = wv;
    }
}

__global__ void copyht_k(float* __restrict__ dst) {
    int i = blockIdx.x * blockDim.x + threadIdx.x;
    if (i < B_ * H_) dst[i] = g_ht[i];
}

// ---------------------------------------------------------------------------
// Launch (only harness pointers cross the host/device boundary)
// ---------------------------------------------------------------------------
extern "C" void kernel_launch(void* const* d_in, const int* in_sizes, int n_in,
                              void* d_out, int out_size) {
    const float* x  = (const float*)d_in[0];
    const float* h0 = (const float*)d_in[1];
    const float* Wi = (const float*)d_in[2];
    const float* bi = (const float*)d_in[3];
    const float* Wh = (const float*)d_in[4];
    const float* bh = (const float*)d_in[5];
    const float* W3 = (const float*)d_in[6];
    const float* b3 = (const float*)d_in[7];
    float* out = (float*)d_out;

    cudaFuncSetAttribute(recur_k, cudaFuncAttributeMaxDynamicSharedMemorySize,
                         RECUR_SMEM);

    // 1. init state + pre-convert operands to tiled bf16 hi/lo
    init_k<<<(B_ * H_ + 255) / 256, 256>>>(h0);
    cvt_x_k<<<(B_ * S_ * I_ / 4 + 255) / 256, 256>>>(x);
    cvt_w_k<H_, I_, 0><<<(H_ * I_ / 4 + 255) / 256, 256>>>(Wi);
    cvt_w_k<O_, H_, 1><<<(O_ * H_ / 4 + 255) / 256, 256>>>(W3);

    // 2. U[t][b][:] = x[b][t][:] @ Wi^T + bi   (t = 0..510)
    gemm_bf<0><<<dim3(H_ / 64, S_ - 1), 256>>>(bi);

    // 3. Serial recurrence (persistent, 128 CTAs, 512 steps, tensor cores)
    recur_k<<<128, 512, RECUR_SMEM>>>(Wh, bh);

    // 4. logits = Z @ W3^T + b3   (g_U reused as logits buffer)
    gemm_bf<1><<<dim3(O_ / 64, (B_ * S_) / 64), 256>>>(b3);

    // 5. softmax -> d_out
    softmax_k<<<(B_ * S_) / 8, 256>>>(out);

    // 6. final hidden state appended after softmax output
    if (out_size >= B_ * S_ * O_ + B_ * H_) {
        copyht_k<<<(B_ * H_ + 255) / 256, 256>>>(out + (long)B_ * S_ * O_);
    }
}

// round 13
// speedup vs baseline: 2.6637x; 1.0124x over previous
#include <cuda_runtime.h>
#include <cuda_bf16.h>

#define B_ 64
#define S_ 512
#define I_ 512
#define H_ 1024
#define O_ 512

// ---------------------------------------------------------------------------
// Static device scratch (no allocations anywhere).
// All bf16 operand arrays use the 8x8-tile-contiguous layout:
//   tile (r>>3, k>>3), 64 halves (128 B) per tile, row-major tiles.
// NOTE: only referenced from device code (host use = shadow-symbol bug, R9/R10).
// ---------------------------------------------------------------------------
__device__ float g_U[(S_ - 1) * B_ * H_];      // U[t][b][j]; reused as logits
__device__ float g_ht[B_ * H_];                // final hidden state (fp32)
__device__ __nv_bfloat16 g_hbf[2][2][B_ * H_]; // [buf][hi/lo] h tiled bf16
__device__ __nv_bfloat16 g_xhi[B_ * S_ * I_];  // x tiled per t: ((t*8+bt)*64+kt)
__device__ __nv_bfloat16 g_xlo[B_ * S_ * I_];
__device__ __nv_bfloat16 g_zhi[B_ * S_ * H_];  // Z rows r=b*512+t: ((r>>3)*128+kt)
__device__ __nv_bfloat16 g_zlo[B_ * S_ * H_];  // t=0 rows never written -> zero
__device__ __nv_bfloat16 g_wihi[H_ * I_];      // Wi tiled ((n>>3)*64+kt)
__device__ __nv_bfloat16 g_wilo[H_ * I_];
__device__ __nv_bfloat16 g_w3hi[O_ * H_];      // W3 tiled ((n>>3)*128+kt)
__device__ __nv_bfloat16 g_w3lo[O_ * H_];
__device__ unsigned g_bar;                     // grid barrier counter

#define HTILE_IDX(b, j) ((((b) >> 3) * 128 + ((j) >> 3)) * 64 + (((b) & 7) << 3) + ((j) & 7))

// ---------------------------------------------------------------------------
// MMA / ldmatrix helpers (bf16, fp32 accum)
// ---------------------------------------------------------------------------
static __device__ __forceinline__ void ldsm_x2(unsigned& r0, unsigned& r1,
                                               unsigned addr) {
    asm volatile("ldmatrix.sync.aligned.m8n8.x2.shared.b16 {%0,%1}, [%2];"
                 : "=r"(r0), "=r"(r1) : "r"(addr));
}
static __device__ __forceinline__ void ldsm_x4(unsigned& r0, unsigned& r1,
                                               unsigned& r2, unsigned& r3,
                                               unsigned addr) {
    asm volatile("ldmatrix.sync.aligned.m8n8.x4.shared.b16 {%0,%1,%2,%3}, [%4];"
                 : "=r"(r0), "=r"(r1), "=r"(r2), "=r"(r3) : "r"(addr));
}
static __device__ __forceinline__ void mma16816(float* c, const unsigned* a,
                                                const unsigned* b) {
    asm volatile("mma.sync.aligned.m16n8k16.row.col.f32.bf16.bf16.f32 "
                 "{%0,%1,%2,%3}, {%4,%5,%6,%7}, {%8,%9}, {%0,%1,%2,%3};"
                 : "+f"(c[0]), "+f"(c[1]), "+f"(c[2]), "+f"(c[3])
                 : "r"(a[0]), "r"(a[1]), "r"(a[2]), "r"(a[3]),
                   "r"(b[0]), "r"(b[1]));
}
// L1-bypass 32-bit global load (h ping-pong is rewritten by other SMs)
static __device__ __forceinline__ unsigned ldcg(const void* p) {
    unsigned v;
    asm volatile("ld.global.cg.b32 %0, [%1];" : "=r"(v) : "l"(p));
    return v;
}

// fp32x4 -> hi/lo bf16x2 pairs written to (tiled) destinations
static __device__ __forceinline__ void cvt_pair(float4 v, __nv_bfloat16* hi,
                                                __nv_bfloat16* lo, long off) {
    __nv_bfloat162 h01 = __float22bfloat162_rn(make_float2(v.x, v.y));
    __nv_bfloat162 h23 = __float22bfloat162_rn(make_float2(v.z, v.w));
    float2 l01f = make_float2(v.x - __bfloat162float(h01.x),
                              v.y - __bfloat162float(h01.y));
    float2 l23f = make_float2(v.z - __bfloat162float(h23.x),
                              v.w - __bfloat162float(h23.y));
    *(__nv_bfloat162*)(hi + off)     = h01;
    *(__nv_bfloat162*)(hi + off + 2) = h23;
    *(__nv_bfloat162*)(lo + off)     = __float22bfloat162_rn(l01f);
    *(__nv_bfloat162*)(lo + off + 2) = __float22bfloat162_rn(l23f);
}

// ---------------------------------------------------------------------------
// Init + conversion kernels
// ---------------------------------------------------------------------------
__global__ void init_k(const float* __restrict__ h0) {
    int i = blockIdx.x * blockDim.x + threadIdx.x;
    if (i < B_ * H_) {
        int b = i >> 10, j = i & 1023;
        float v = h0[i];
        __nv_bfloat16 hi = __float2bfloat16(v);
        __nv_bfloat16 lo = __float2bfloat16(v - __bfloat162float(hi));
        int idx = HTILE_IDX(b, j);
        g_hbf[0][0][idx] = hi;
        g_hbf[0][1][idx] = lo;
    }
    if (i == 0) g_bar = 0u;
}

// x[b][t][k] -> per-t tiled: tile (t*8 + b>>3, k>>3)
__global__ void cvt_x_k(const float* __restrict__ x) {
    long i4 = (long)blockIdx.x * blockDim.x + threadIdx.x;
    if (i4 >= (long)B_ * S_ * I_ / 4) return;
    long e = i4 << 2;
    int b = (int)(e >> 18);
    int rem = (int)(e & 262143);
    int t = rem >> 9;
    int k = rem & 511;
    float4 v = *(const float4*)&x[e];
    long off = ((long)((t << 3) + (b >> 3)) * 64 + (k >> 3)) * 64
             + ((b & 7) << 3) + (k & 7);
    cvt_pair(v, g_xhi, g_xlo, off);
}

// W[n][k] (NR x NC) -> tiled; WHICH selects destination (device-side!)
template <int NR, int NC, int WHICH>
__global__ void cvt_w_k(const float* __restrict__ W) {
    __nv_bfloat16* hi = (WHICH == 0) ? g_wihi : g_w3hi;
    __nv_bfloat16* lo = (WHICH == 0) ? g_wilo : g_w3lo;
    int i4 = blockIdx.x * blockDim.x + threadIdx.x;
    if (i4 >= NR * NC / 4) return;
    int e = i4 << 2;
    int n = e / NC, k = e % NC;
    float4 v = *(const float4*)&W[e];
    long off = ((long)(n >> 3) * (NC / 8) + (k >> 3)) * 64 + ((n & 7) << 3) + (k & 7);
    cvt_pair(v, hi, lo, off);
}

// ---------------------------------------------------------------------------
// Pure-bf16 tensor GEMM, K-chunk 32 (2 k-subchunks per stage iteration):
// halves stage iterations + syncthreads vs K-chunk 16. 64x64 CTA tile,
// 256 thr = 8 warps (2m x 4n), double-buffered cp.async, operands selected
// inside device code by MODE.
//   MODE 0: U = x_t @ Wi^T + bi   (A = g_x*, W = g_wi*, K=512,  N=1024)
//   MODE 1: logits = Z @ W3^T+b3  (A = g_z*, W = g_w3*, K=1024, N=512)
// SMEM layout per buffer (16KB): [Ahi|Alo|Whi|Wlo] x 32 tiles x 128B,
// tile index tl = row_tile*4 + k_tile  (k_tile 0..3 within the 32-k chunk).
// ---------------------------------------------------------------------------
template <int MODE>
__global__ __launch_bounds__(256) void gemm_bf(const float* __restrict__ bias) {
    constexpr int K = (MODE == 0) ? I_ : H_;
    constexpr int N = (MODE == 0) ? H_ : O_;
    constexpr int NCHUNK = K / 32;
    constexpr int KT = K / 8;

    const __nv_bfloat16* Ahi = (MODE == 0) ? g_xhi : g_zhi;
    const __nv_bfloat16* Alo = (MODE == 0) ? g_xlo : g_zlo;
    const __nv_bfloat16* Whi = (MODE == 0) ? g_wihi : g_w3hi;
    const __nv_bfloat16* Wlo = (MODE == 0) ? g_wilo : g_w3lo;

    __shared__ __align__(16) __nv_bfloat16 sbuf[2][8192];   // 32KB total

    const int tid  = threadIdx.x;
    const int lane = tid & 31;
    const int wid  = tid >> 5;
    const int wm   = wid & 1;
    const int wn   = wid >> 1;
    const int n0   = blockIdx.x * 64;
    const int y    = blockIdx.y;

    const unsigned sbase = (unsigned)__cvta_generic_to_shared(&sbuf[0][0]);

    // stage one 32-k chunk: 1024 x 16B cp.asyncs (4 per thread)
    auto stage = [&](int c, int bufp) {
#pragma unroll
        for (int e = 0; e < 4; ++e) {
            int ci = tid + (e << 8);          // 0..1023
            int a  = ci >> 8;                 // 0 Ahi,1 Alo,2 Whi,3 Wlo
            int tl = (ci & 255) >> 3;         // 0..31: bt*4 + ktl
            int bt = tl >> 2, ktl = tl & 3;
            int kt = (c << 2) + ktl;
            int inner = (ci & 7) << 4;
            long tileIdx = (a < 2) ? ((long)((y << 3) + bt) * KT + kt)
                                   : ((long)((n0 >> 3) + bt) * KT + kt);
            const __nv_bfloat16* src =
                (a == 0 ? Ahi : a == 1 ? Alo : a == 2 ? Whi : Wlo);
            const char* gsrc = (const char*)src + tileIdx * 128 + inner;
            unsigned dst = sbase + (unsigned)(bufp * 16384 + a * 4096 + tl * 128 + inner);
            asm volatile("cp.async.cg.shared.global [%0], [%1], 16;"
                         :: "r"(dst), "l"(gsrc));
        }
    };

    float acc[2][2][4];
#pragma unroll
    for (int i = 0; i < 2; ++i)
#pragma unroll
        for (int j = 0; j < 2; ++j)
#pragma unroll
            for (int q = 0; q < 4; ++q) acc[i][j][q] = 0.f;

    const int g4   = lane >> 3;
    const int g2   = g4 & 1;
    const int rowi = (lane & 7) << 4;

    stage(0, 0);
    asm volatile("cp.async.commit_group;");

    for (int c = 0; c < NCHUNK; ++c) {
        const int cur = c & 1;
        if (c + 1 < NCHUNK) {
            stage(c + 1, cur ^ 1);
            asm volatile("cp.async.commit_group;");
            asm volatile("cp.async.wait_group 1;" ::: "memory");
        } else {
            asm volatile("cp.async.wait_group 0;" ::: "memory");
        }
        __syncthreads();

        const unsigned bA0 = sbase + (unsigned)(cur * 16384);
        const unsigned bA1 = bA0 + 4096;
        const unsigned bW0 = bA0 + 8192;
        const unsigned bW1 = bA0 + 12288;

#pragma unroll
        for (int ks = 0; ks < 2; ++ks) {
            unsigned ahi[2][4], alo[2][4], bhi[2][2], blo[2][2];
#pragma unroll
            for (int mf = 0; mf < 2; ++mf) {
                int mi = wm * 4 + mf * 2;
                unsigned ti  = (unsigned)((mi + (g4 & 1)) * 4 + (ks << 1) + (g4 >> 1));
                unsigned off = ti * 128u + rowi;
                ldsm_x4(ahi[mf][0], ahi[mf][1], ahi[mf][2], ahi[mf][3], bA0 + off);
                ldsm_x4(alo[mf][0], alo[mf][1], alo[mf][2], alo[mf][3], bA1 + off);
            }
#pragma unroll
            for (int nf = 0; nf < 2; ++nf) {
                int ni = wn * 2 + nf;
                unsigned ti  = (unsigned)(ni * 4 + (ks << 1) + g2);
                unsigned off = ti * 128u + rowi;
                ldsm_x2(bhi[nf][0], bhi[nf][1], bW0 + off);
                ldsm_x2(blo[nf][0], blo[nf][1], bW1 + off);
            }
#pragma unroll
            for (int mf = 0; mf < 2; ++mf)
#pragma unroll
                for (int nf = 0; nf < 2; ++nf) {
                    mma16816(acc[mf][nf], ahi[mf], bhi[nf]);
                    mma16816(acc[mf][nf], ahi[mf], blo[nf]);
                    mma16816(acc[mf][nf], alo[mf], bhi[nf]);
                }
        }
        __syncthreads();
    }

#pragma unroll
    for (int nf = 0; nf < 2; ++nf) {
        int bcol = n0 + wn * 16 + nf * 8 + ((lane & 3) << 1);
        float2 bv = *(const float2*)&bias[bcol];
#pragma unroll
        for (int mf = 0; mf < 2; ++mf) {
            long r0 = (long)(y << 6) + wm * 32 + mf * 16 + (lane >> 2);
            float2 o0 = make_float2(acc[mf][nf][0] + bv.x, acc[mf][nf][1] + bv.y);
            float2 o1 = make_float2(acc[mf][nf][2] + bv.x, acc[mf][nf][3] + bv.y);
            *(float2*)&g_U[r0 * N + bcol]       = o0;
            *(float2*)&g_U[(r0 + 8) * N + bcol] = o1;
        }
    }
}

// ---------------------------------------------------------------------------
// Persistent recurrence kernel v10 — tensor cores, direct-from-global
// A fragments (ld.global.cg, ldmatrix-by-LDG emulation), Wh B-fragments in
// registers, U prefetched for the NEXT step during the barrier-spin window
// (moves its LDG out of the post-barrier LSU burst).
// ---------------------------------------------------------------------------
#define PSTRIDE 34
#define RECUR_SMEM (16384 * 2 * 2 + 16 * 16 * PSTRIDE * 4)

__global__ void __launch_bounds__(512, 1) recur_k(const float* __restrict__ Wh,
                                                  const float* __restrict__ bh) {
    extern __shared__ char smraw[];
    __nv_bfloat16* hsH = (__nv_bfloat16*)smraw;          // setup temp only
    float* part = (float*)(smraw + 65536);               // [16][16][PSTRIDE]

    const int tid = threadIdx.x;
    const int w   = tid >> 5;            // warp 0..15 -> k slice [w*64, +64)
    const int l   = tid & 31;
    const int cb  = blockIdx.x;
    const int j0  = (cb & 31) << 5;
    const int bg  = cb >> 5;
    const int b0  = bg << 4;
    const int j   = j0 + l;

    const unsigned baseW = (unsigned)__cvta_generic_to_shared(hsH);

    // ---- setup: Wh -> split-bf16 B fragments in registers (two passes) ----
    unsigned Bhi[4][4][2], Blo[4][4][2];
    {
        __nv_bfloat16* wtmp = hsH;
#pragma unroll 1
        for (int pass = 0; pass < 2; ++pass) {
#pragma unroll 1
            for (int it = 0; it < 16; ++it) {
                int e  = tid + (it << 9);
                int jj = e >> 8;
                int k  = (e & 255) << 2;
                float4 f = *(const float4*)&Wh[(long)(j0 + jj) * H_ + k];
                __nv_bfloat162 p01, p23;
                if (pass == 0) {
                    p01 = __float22bfloat162_rn(make_float2(f.x, f.y));
                    p23 = __float22bfloat162_rn(make_float2(f.z, f.w));
                } else {
                    __nv_bfloat162 h01 = __float22bfloat162_rn(make_float2(f.x, f.y));
                    __nv_bfloat162 h23 = __float22bfloat162_rn(make_float2(f.z, f.w));
                    p01 = __float22bfloat162_rn(make_float2(
                        f.x - __bfloat162float(h01.x), f.y - __bfloat162float(h01.y)));
                    p23 = __float22bfloat162_rn(make_float2(
                        f.z - __bfloat162float(h23.x), f.w - __bfloat162float(h23.y)));
                }
                int off = ((jj >> 3) * 128 + (k >> 3)) * 64 + ((jj & 7) << 3) + (k & 7);
                *(__nv_bfloat162*)(wtmp + off)     = p01;
                *(__nv_bfloat162*)(wtmp + off + 2) = p23;
            }
            __syncthreads();
#pragma unroll
            for (int s = 0; s < 4; ++s) {
                int kt0 = (w << 3) + (s << 1);
#pragma unroll
                for (int nt = 0; nt < 4; ++nt) {
                    unsigned addr = baseW +
                        (unsigned)(((nt * 128 + kt0 + ((l >> 3) & 1)) << 7) + ((l & 7) << 4));
                    if (pass == 0) ldsm_x2(Bhi[s][nt][0], Bhi[s][nt][1], addr);
                    else           ldsm_x2(Blo[s][nt][0], Blo[s][nt][1], addr);
                }
            }
            __syncthreads();
        }
    }

    const int rb = tid >> 5;
    const int gb = b0 + rb;
    const float bhj = bh[j];
    const int inner = ((l >> 2) << 4) + ((l & 3) << 2);   // frag byte in tile

    // U prefetch for step 0 (steps use u at m <= S_-2)
    float u_next = g_U[(long)(0 * 64 + gb) * H_ + j];

    for (int m = 0; m < S_; ++m) {
        const char* hH = (const char*)(g_hbf[m & 1][0] + (bg << 14));
        const char* hL = (const char*)(g_hbf[m & 1][1] + (bg << 14));

        // fragment loader: k-step s -> tiles (bt, kt), (bt, kt+1), kt = w*8+2s
        auto loadfrag = [&](int s, unsigned* aH, unsigned* aL) {
            int kt = (w << 3) + (s << 1);
            int o00 = (kt << 7) + inner;      // bt0, kt
            int o10 = o00 + 16384;            // bt1, kt   (+128 tiles)
            aH[0] = ldcg(hH + o00); aH[1] = ldcg(hH + o10);
            aH[2] = ldcg(hH + o00 + 128); aH[3] = ldcg(hH + o10 + 128);
            aL[0] = ldcg(hL + o00); aL[1] = ldcg(hL + o10);
            aL[2] = ldcg(hL + o00 + 128); aL[3] = ldcg(hL + o10 + 128);
        };

        const float u0 = u_next;   // valid when m <= S_-2

        float acc[4][4];
#pragma unroll
        for (int nt = 0; nt < 4; ++nt)
#pragma unroll
            for (int q = 0; q < 4; ++q) acc[nt][q] = 0.f;

        unsigned aH[2][4], aL[2][4];
        loadfrag(0, aH[0], aL[0]);
#pragma unroll
        for (int s = 0; s < 4; ++s) {
            const int cur = s & 1;
            if (s < 3) loadfrag(s + 1, aH[cur ^ 1], aL[cur ^ 1]);
#pragma unroll
            for (int nt = 0; nt < 4; ++nt) {
                mma16816(acc[nt], aH[cur], Bhi[s][nt]);
                mma16816(acc[nt], aH[cur], Blo[s][nt]);
                mma16816(acc[nt], aL[cur], Bhi[s][nt]);
            }
        }

        // ---- store partials (padded stride -> conflict-free) ----
        {
            float* pw = part + w * (16 * PSTRIDE);
            int prow = l >> 2, pcol = (l & 3) << 1;
#pragma unroll
            for (int nt = 0; nt < 4; ++nt) {
                *(float2*)&pw[prow * PSTRIDE + nt * 8 + pcol] =
                    make_float2(acc[nt][0], acc[nt][1]);
                *(float2*)&pw[(prow + 8) * PSTRIDE + nt * 8 + pcol] =
                    make_float2(acc[nt][2], acc[nt][3]);
            }
        }
        __syncthreads();

        // ---- reduce 16 k-slices, bias, tanh, h write (bf16 hi/lo) ----
        float av;
        {
            float s = 0.f;
#pragma unroll
            for (int ww = 0; ww < 16; ++ww)
                s += part[ww * (16 * PSTRIDE) + rb * PSTRIDE + l];
            av = s + bhj;
            if (m <= S_ - 2) {
                float hv = tanhf(u0 + av);
                __nv_bfloat16 hi = __float2bfloat16(hv);
                __nv_bfloat16 lo = __float2bfloat16(hv - __bfloat162float(hi));
                int idx = HTILE_IDX(gb, j);
                g_hbf[(m + 1) & 1][0][idx] = hi;
                g_hbf[(m + 1) & 1][1][idx] = lo;
                if (m == S_ - 2) g_ht[gb * H_ + j] = hv;
            }
        }

        // z write target (tiled bf16, rows r = b*512 + t)
        const int zr = (gb << 9) + m;
        const long zt = ((long)(zr >> 3) * 128 + (j >> 3)) * 64
                      + ((zr & 7) << 3) + (j & 7);

        if (m != S_ - 1) {
            __syncthreads();
            if (tid == 0) {
                __threadfence();
                atomicAdd(&g_bar, 1u);
            }
            // barrier window: z tanh + bf16 store AND next-step U prefetch
            if (m >= 1) {
                float zv = tanhf(av);
                __nv_bfloat16 zh = __float2bfloat16(zv);
                g_zhi[zt] = zh;
                g_zlo[zt] = __float2bfloat16(zv - __bfloat162float(zh));
            }
            if (m + 1 <= S_ - 2)
                u_next = g_U[((long)(m + 1) * 64 + gb) * H_ + j];
            if (tid == 0) {
                unsigned target = (unsigned)(128 * (m + 1));
                unsigned v;
                do {
                    asm volatile("ld.acquire.gpu.global.u32 %0, [%1];"
                                 : "=r"(v) : "l"(&g_bar));
                } while (v < target);
            }
            __syncthreads();
        } else {
            float zv = tanhf(av);
            __nv_bfloat16 zh = __float2bfloat16(zv);
            g_zhi[zt] = zh;
            g_zlo[zt] = __float2bfloat16(zv - __bfloat162float(zh));
        }
    }
}

// ---------------------------------------------------------------------------
// Row softmax over O_=512 cols; warp per row, logits read from g_U (reused).
// ---------------------------------------------------------------------------
__global__ __launch_bounds__(256) void softmax_k(float* __restrict__ out) {
    int r = blockIdx.x * 8 + (threadIdx.x >> 5);
    int l = threadIdx.x & 31;
    const float* row = g_U + (long)r * O_;

    float4 v[4];
    float mx = -3.0e38f;
#pragma unroll
    for (int q = 0; q < 4; ++q) {
        v[q] = *(const float4*)&row[(l + (q << 5)) << 2];
        mx = fmaxf(mx, fmaxf(fmaxf(v[q].x, v[q].y), fmaxf(v[q].z, v[q].w)));
    }
#pragma unroll
    for (int o = 16; o; o >>= 1) mx = fmaxf(mx, __shfl_xor_sync(~0u, mx, o));

    float s = 0.f;
#pragma unroll
    for (int q = 0; q < 4; ++q) {
        v[q].x = expf(v[q].x - mx); v[q].y = expf(v[q].y - mx);
        v[q].z = expf(v[q].z - mx); v[q].w = expf(v[q].w - mx);
        s += (v[q].x + v[q].y) + (v[q].z + v[q].w);
    }
#pragma unroll
    for (int o = 16; o; o >>= 1) s += __shfl_xor_sync(~0u, s, o);
    float inv = 1.0f / s;

#pragma unroll
    for (int q = 0; q < 4; ++q) {
        float4 wv = make_float4(v[q].x * inv, v[q].y * inv, v[q].z * inv, v[q].w * inv);
        *(float4*)&out[(long)r * O_ + ((l + (q << 5)) << 2)] = wv;
    }
}

__global__ void copyht_k(float* __restrict__ dst) {
    int i = blockIdx.x * blockDim.x + threadIdx.x;
    if (i < B_ * H_) dst[i] = g_ht[i];
}

// ---------------------------------------------------------------------------
// Launch (only harness pointers cross the host/device boundary)
// ---------------------------------------------------------------------------
extern "C" void kernel_launch(void* const* d_in, const int* in_sizes, int n_in,
                              void* d_out, int out_size) {
    const float* x  = (const float*)d_in[0];
    const float* h0 = (const float*)d_in[1];
    const float* Wi = (const float*)d_in[2];
    const float* bi = (const float*)d_in[3];
    const float* Wh = (const float*)d_in[4];
    const float* bh = (const float*)d_in[5];
    const float* W3 = (const float*)d_in[6];
    const float* b3 = (const float*)d_in[7];
    float* out = (float*)d_out;

    cudaFuncSetAttribute(recur_k, cudaFuncAttributeMaxDynamicSharedMemorySize,
                         RECUR_SMEM);

    // 1. init state + pre-convert operands to tiled bf16 hi/lo
    init_k<<<(B_ * H_ + 255) / 256, 256>>>(h0);
    cvt_x_k<<<(B_ * S_ * I_ / 4 + 255) / 256, 256>>>(x);
    cvt_w_k<H_, I_, 0><<<(H_ * I_ / 4 + 255) / 256, 256>>>(Wi);
    cvt_w_k<O_, H_, 1><<<(O_ * H_ / 4 + 255) / 256, 256>>>(W3);

    // 2. U[t][b][:] = x[b][t][:] @ Wi^T + bi   (t = 0..510)
    gemm_bf<0><<<dim3(H_ / 64, S_ - 1), 256>>>(bi);

    // 3. Serial recurrence (persistent, 128 CTAs, 512 steps, tensor cores)
    recur_k<<<128, 512, RECUR_SMEM>>>(Wh, bh);

    // 4. logits = Z @ W3^T + b3   (g_U reused as logits buffer)
    gemm_bf<1><<<dim3(O_ / 64, (B_ * S_) / 64), 256>>>(b3);

    // 5. softmax -> d_out
    softmax_k<<<(B_ * S_) / 8, 256>>>(out);

    // 6. final hidden state appended after softmax output
    if (out_size >= B_ * S_ * O_ + B_ * H_) {
        copyht_k<<<(B_ * H_ + 255) / 256, 256>>>(out + (long)B_ * S_ * O_);
    }
}

// round 14
// speedup vs baseline: 2.7831x; 1.0448x over previous
#include <cuda_runtime.h>
#include <cuda_bf16.h>

#define B_ 64
#define S_ 512
#define I_ 512
#define H_ 1024
#define O_ 512

// ---------------------------------------------------------------------------
// Static device scratch (no allocations anywhere).
// All bf16 operand arrays use the 8x8-tile-contiguous layout:
//   tile (r>>3, k>>3), 64 halves (128 B) per tile, row-major tiles.
// NOTE: only referenced from device code (host use = shadow-symbol bug, R9/R10).
// ---------------------------------------------------------------------------
__device__ float g_U[(S_ - 1) * B_ * H_];      // U[t][b][j]; reused as logits
__device__ float g_ht[B_ * H_];                // final hidden state (fp32)
__device__ __nv_bfloat16 g_hbf[2][2][B_ * H_]; // [buf][hi/lo] h tiled bf16
__device__ __nv_bfloat16 g_xhi[B_ * S_ * I_];  // x tiled per t: ((t*8+bt)*64+kt)
__device__ __nv_bfloat16 g_xlo[B_ * S_ * I_];
__device__ __nv_bfloat16 g_zhi[B_ * S_ * H_];  // Z rows r=b*512+t: ((r>>3)*128+kt)
__device__ __nv_bfloat16 g_zlo[B_ * S_ * H_];  // t=0 rows never written -> zero
__device__ __nv_bfloat16 g_wihi[H_ * I_];      // Wi tiled ((n>>3)*64+kt)
__device__ __nv_bfloat16 g_wilo[H_ * I_];
__device__ __nv_bfloat16 g_w3hi[O_ * H_];      // W3 tiled ((n>>3)*128+kt)
__device__ __nv_bfloat16 g_w3lo[O_ * H_];
__device__ unsigned g_bar4[4 * 32];            // per-bgroup barrier counters,
                                               // 128B apart (idx bg*32)

#define HTILE_IDX(b, j) ((((b) >> 3) * 128 + ((j) >> 3)) * 64 + (((b) & 7) << 3) + ((j) & 7))

// ---------------------------------------------------------------------------
// MMA / ldmatrix helpers (bf16, fp32 accum)
// ---------------------------------------------------------------------------
static __device__ __forceinline__ void ldsm_x2(unsigned& r0, unsigned& r1,
                                               unsigned addr) {
    asm volatile("ldmatrix.sync.aligned.m8n8.x2.shared.b16 {%0,%1}, [%2];"
                 : "=r"(r0), "=r"(r1) : "r"(addr));
}
static __device__ __forceinline__ void ldsm_x4(unsigned& r0, unsigned& r1,
                                               unsigned& r2, unsigned& r3,
                                               unsigned addr) {
    asm volatile("ldmatrix.sync.aligned.m8n8.x4.shared.b16 {%0,%1,%2,%3}, [%4];"
                 : "=r"(r0), "=r"(r1), "=r"(r2), "=r"(r3) : "r"(addr));
}
static __device__ __forceinline__ void mma16816(float* c, const unsigned* a,
                                                const unsigned* b) {
    asm volatile("mma.sync.aligned.m16n8k16.row.col.f32.bf16.bf16.f32 "
                 "{%0,%1,%2,%3}, {%4,%5,%6,%7}, {%8,%9}, {%0,%1,%2,%3};"
                 : "+f"(c[0]), "+f"(c[1]), "+f"(c[2]), "+f"(c[3])
                 : "r"(a[0]), "r"(a[1]), "r"(a[2]), "r"(a[3]),
                   "r"(b[0]), "r"(b[1]));
}
// L1-bypass 32-bit global load (h ping-pong is rewritten by other SMs)
static __device__ __forceinline__ unsigned ldcg(const void* p) {
    unsigned v;
    asm volatile("ld.global.cg.b32 %0, [%1];" : "=r"(v) : "l"(p));
    return v;
}

// fp32x4 -> hi/lo bf16x2 pairs written to (tiled) destinations
static __device__ __forceinline__ void cvt_pair(float4 v, __nv_bfloat16* hi,
                                                __nv_bfloat16* lo, long off) {
    __nv_bfloat162 h01 = __float22bfloat162_rn(make_float2(v.x, v.y));
    __nv_bfloat162 h23 = __float22bfloat162_rn(make_float2(v.z, v.w));
    float2 l01f = make_float2(v.x - __bfloat162float(h01.x),
                              v.y - __bfloat162float(h01.y));
    float2 l23f = make_float2(v.z - __bfloat162float(h23.x),
                              v.w - __bfloat162float(h23.y));
    *(__nv_bfloat162*)(hi + off)     = h01;
    *(__nv_bfloat162*)(hi + off + 2) = h23;
    *(__nv_bfloat162*)(lo + off)     = __float22bfloat162_rn(l01f);
    *(__nv_bfloat162*)(lo + off + 2) = __float22bfloat162_rn(l23f);
}

// ---------------------------------------------------------------------------
// Init + conversion kernels
// ---------------------------------------------------------------------------
__global__ void init_k(const float* __restrict__ h0) {
    int i = blockIdx.x * blockDim.x + threadIdx.x;
    if (i < B_ * H_) {
        int b = i >> 10, j = i & 1023;
        float v = h0[i];
        __nv_bfloat16 hi = __float2bfloat16(v);
        __nv_bfloat16 lo = __float2bfloat16(v - __bfloat162float(hi));
        int idx = HTILE_IDX(b, j);
        g_hbf[0][0][idx] = hi;
        g_hbf[0][1][idx] = lo;
    }
    if (i < 4 * 32) g_bar4[i] = 0u;
}

// x[b][t][k] -> per-t tiled: tile (t*8 + b>>3, k>>3)
__global__ void cvt_x_k(const float* __restrict__ x) {
    long i4 = (long)blockIdx.x * blockDim.x + threadIdx.x;
    if (i4 >= (long)B_ * S_ * I_ / 4) return;
    long e = i4 << 2;
    int b = (int)(e >> 18);
    int rem = (int)(e & 262143);
    int t = rem >> 9;
    int k = rem & 511;
    float4 v = *(const float4*)&x[e];
    long off = ((long)((t << 3) + (b >> 3)) * 64 + (k >> 3)) * 64
             + ((b & 7) << 3) + (k & 7);
    cvt_pair(v, g_xhi, g_xlo, off);
}

// W[n][k] (NR x NC) -> tiled; WHICH selects destination (device-side!)
template <int NR, int NC, int WHICH>
__global__ void cvt_w_k(const float* __restrict__ W) {
    __nv_bfloat16* hi = (WHICH == 0) ? g_wihi : g_w3hi;
    __nv_bfloat16* lo = (WHICH == 0) ? g_wilo : g_w3lo;
    int i4 = blockIdx.x * blockDim.x + threadIdx.x;
    if (i4 >= NR * NC / 4) return;
    int e = i4 << 2;
    int n = e / NC, k = e % NC;
    float4 v = *(const float4*)&W[e];
    long off = ((long)(n >> 3) * (NC / 8) + (k >> 3)) * 64 + ((n & 7) << 3) + (k & 7);
    cvt_pair(v, hi, lo, off);
}

// ---------------------------------------------------------------------------
// Pure-bf16 tensor GEMM, K-chunk 32. 64x64 CTA tile, 256 thr = 8 warps
// (2m x 4n), double-buffered cp.async, operands selected by MODE in device code.
//   MODE 0: U = x_t @ Wi^T + bi   (A = g_x*, W = g_wi*, K=512,  N=1024)
//   MODE 1: logits = Z @ W3^T+b3  (A = g_z*, W = g_w3*, K=1024, N=512)
// ---------------------------------------------------------------------------
template <int MODE>
__global__ __launch_bounds__(256) void gemm_bf(const float* __restrict__ bias) {
    constexpr int K = (MODE == 0) ? I_ : H_;
    constexpr int N = (MODE == 0) ? H_ : O_;
    constexpr int NCHUNK = K / 32;
    constexpr int KT = K / 8;

    const __nv_bfloat16* Ahi = (MODE == 0) ? g_xhi : g_zhi;
    const __nv_bfloat16* Alo = (MODE == 0) ? g_xlo : g_zlo;
    const __nv_bfloat16* Whi = (MODE == 0) ? g_wihi : g_w3hi;
    const __nv_bfloat16* Wlo = (MODE == 0) ? g_wilo : g_w3lo;

    __shared__ __align__(16) __nv_bfloat16 sbuf[2][8192];

    const int tid  = threadIdx.x;
    const int lane = tid & 31;
    const int wid  = tid >> 5;
    const int wm   = wid & 1;
    const int wn   = wid >> 1;
    const int n0   = blockIdx.x * 64;
    const int y    = blockIdx.y;

    const unsigned sbase = (unsigned)__cvta_generic_to_shared(&sbuf[0][0]);

    auto stage = [&](int c, int bufp) {
#pragma unroll
        for (int e = 0; e < 4; ++e) {
            int ci = tid + (e << 8);
            int a  = ci >> 8;
            int tl = (ci & 255) >> 3;
            int bt = tl >> 2, ktl = tl & 3;
            int kt = (c << 2) + ktl;
            int inner = (ci & 7) << 4;
            long tileIdx = (a < 2) ? ((long)((y << 3) + bt) * KT + kt)
                                   : ((long)((n0 >> 3) + bt) * KT + kt);
            const __nv_bfloat16* src =
                (a == 0 ? Ahi : a == 1 ? Alo : a == 2 ? Whi : Wlo);
            const char* gsrc = (const char*)src + tileIdx * 128 + inner;
            unsigned dst = sbase + (unsigned)(bufp * 16384 + a * 4096 + tl * 128 + inner);
            asm volatile("cp.async.cg.shared.global [%0], [%1], 16;"
                         :: "r"(dst), "l"(gsrc));
        }
    };

    float acc[2][2][4];
#pragma unroll
    for (int i = 0; i < 2; ++i)
#pragma unroll
        for (int j = 0; j < 2; ++j)
#pragma unroll
            for (int q = 0; q < 4; ++q) acc[i][j][q] = 0.f;

    const int g4   = lane >> 3;
    const int g2   = g4 & 1;
    const int rowi = (lane & 7) << 4;

    stage(0, 0);
    asm volatile("cp.async.commit_group;");

    for (int c = 0; c < NCHUNK; ++c) {
        const int cur = c & 1;
        if (c + 1 < NCHUNK) {
            stage(c + 1, cur ^ 1);
            asm volatile("cp.async.commit_group;");
            asm volatile("cp.async.wait_group 1;" ::: "memory");
        } else {
            asm volatile("cp.async.wait_group 0;" ::: "memory");
        }
        __syncthreads();

        const unsigned bA0 = sbase + (unsigned)(cur * 16384);
        const unsigned bA1 = bA0 + 4096;
        const unsigned bW0 = bA0 + 8192;
        const unsigned bW1 = bA0 + 12288;

#pragma unroll
        for (int ks = 0; ks < 2; ++ks) {
            unsigned ahi[2][4], alo[2][4], bhi[2][2], blo[2][2];
#pragma unroll
            for (int mf = 0; mf < 2; ++mf) {
                int mi = wm * 4 + mf * 2;
                unsigned ti  = (unsigned)((mi + (g4 & 1)) * 4 + (ks << 1) + (g4 >> 1));
                unsigned off = ti * 128u + rowi;
                ldsm_x4(ahi[mf][0], ahi[mf][1], ahi[mf][2], ahi[mf][3], bA0 + off);
                ldsm_x4(alo[mf][0], alo[mf][1], alo[mf][2], alo[mf][3], bA1 + off);
            }
#pragma unroll
            for (int nf = 0; nf < 2; ++nf) {
                int ni = wn * 2 + nf;
                unsigned ti  = (unsigned)(ni * 4 + (ks << 1) + g2);
                unsigned off = ti * 128u + rowi;
                ldsm_x2(bhi[nf][0], bhi[nf][1], bW0 + off);
                ldsm_x2(blo[nf][0], blo[nf][1], bW1 + off);
            }
#pragma unroll
            for (int mf = 0; mf < 2; ++mf)
#pragma unroll
                for (int nf = 0; nf < 2; ++nf) {
                    mma16816(acc[mf][nf], ahi[mf], bhi[nf]);
                    mma16816(acc[mf][nf], ahi[mf], blo[nf]);
                    mma16816(acc[mf][nf], alo[mf], bhi[nf]);
                }
        }
        __syncthreads();
    }

#pragma unroll
    for (int nf = 0; nf < 2; ++nf) {
        int bcol = n0 + wn * 16 + nf * 8 + ((lane & 3) << 1);
        float2 bv = *(const float2*)&bias[bcol];
#pragma unroll
        for (int mf = 0; mf < 2; ++mf) {
            long r0 = (long)(y << 6) + wm * 32 + mf * 16 + (lane >> 2);
            float2 o0 = make_float2(acc[mf][nf][0] + bv.x, acc[mf][nf][1] + bv.y);
            float2 o1 = make_float2(acc[mf][nf][2] + bv.x, acc[mf][nf][3] + bv.y);
            *(float2*)&g_U[r0 * N + bcol]       = o0;
            *(float2*)&g_U[(r0 + 8) * N + bcol] = o1;
        }
    }
}

// ---------------------------------------------------------------------------
// Persistent recurrence kernel v11 — tensor cores, direct-from-global A
// fragments, Wh B-fragments in registers, U prefetch in barrier window,
// and PER-BGROUP barriers: the 4 b-group chains are independent, so each
// group of 32 CTAs synchronizes on its own padded counter with a fused
// release-atomic (red.release.gpu) — no cross-group straggler coupling.
// ---------------------------------------------------------------------------
#define PSTRIDE 34
#define RECUR_SMEM (16384 * 2 * 2 + 16 * 16 * PSTRIDE * 4)

__global__ void __launch_bounds__(512, 1) recur_k(const float* __restrict__ Wh,
                                                  const float* __restrict__ bh) {
    extern __shared__ char smraw[];
    __nv_bfloat16* hsH = (__nv_bfloat16*)smraw;          // setup temp only
    float* part = (float*)(smraw + 65536);               // [16][16][PSTRIDE]

    const int tid = threadIdx.x;
    const int w   = tid >> 5;            // warp 0..15 -> k slice [w*64, +64)
    const int l   = tid & 31;
    const int cb  = blockIdx.x;
    const int j0  = (cb & 31) << 5;
    const int bg  = cb >> 5;
    const int b0  = bg << 4;
    const int j   = j0 + l;
    unsigned* bar = &g_bar4[bg << 5];    // this group's padded counter

    const unsigned baseW = (unsigned)__cvta_generic_to_shared(hsH);

    // ---- setup: Wh -> split-bf16 B fragments in registers (two passes) ----
    unsigned Bhi[4][4][2], Blo[4][4][2];
    {
        __nv_bfloat16* wtmp = hsH;
#pragma unroll 1
        for (int pass = 0; pass < 2; ++pass) {
#pragma unroll 1
            for (int it = 0; it < 16; ++it) {
                int e  = tid + (it << 9);
                int jj = e >> 8;
                int k  = (e & 255) << 2;
                float4 f = *(const float4*)&Wh[(long)(j0 + jj) * H_ + k];
                __nv_bfloat162 p01, p23;
                if (pass == 0) {
                    p01 = __float22bfloat162_rn(make_float2(f.x, f.y));
                    p23 = __float22bfloat162_rn(make_float2(f.z, f.w));
                } else {
                    __nv_bfloat162 h01 = __float22bfloat162_rn(make_float2(f.x, f.y));
                    __nv_bfloat162 h23 = __float22bfloat162_rn(make_float2(f.z, f.w));
                    p01 = __float22bfloat162_rn(make_float2(
                        f.x - __bfloat162float(h01.x), f.y - __bfloat162float(h01.y)));
                    p23 = __float22bfloat162_rn(make_float2(
                        f.z - __bfloat162float(h23.x), f.w - __bfloat162float(h23.y)));
                }
                int off = ((jj >> 3) * 128 + (k >> 3)) * 64 + ((jj & 7) << 3) + (k & 7);
                *(__nv_bfloat162*)(wtmp + off)     = p01;
                *(__nv_bfloat162*)(wtmp + off + 2) = p23;
            }
            __syncthreads();
#pragma unroll
            for (int s = 0; s < 4; ++s) {
                int kt0 = (w << 3) + (s << 1);
#pragma unroll
                for (int nt = 0; nt < 4; ++nt) {
                    unsigned addr = baseW +
                        (unsigned)(((nt * 128 + kt0 + ((l >> 3) & 1)) << 7) + ((l & 7) << 4));
                    if (pass == 0) ldsm_x2(Bhi[s][nt][0], Bhi[s][nt][1], addr);
                    else           ldsm_x2(Blo[s][nt][0], Blo[s][nt][1], addr);
                }
            }
            __syncthreads();
        }
    }

    const int rb = tid >> 5;
    const int gb = b0 + rb;
    const float bhj = bh[j];
    const int inner = ((l >> 2) << 4) + ((l & 3) << 2);   // frag byte in tile

    // U prefetch for step 0
    float u_next = g_U[(long)(0 * 64 + gb) * H_ + j];

    for (int m = 0; m < S_; ++m) {
        const char* hH = (const char*)(g_hbf[m & 1][0] + (bg << 14));
        const char* hL = (const char*)(g_hbf[m & 1][1] + (bg << 14));

        auto loadfrag = [&](int s, unsigned* aH, unsigned* aL) {
            int kt = (w << 3) + (s << 1);
            int o00 = (kt << 7) + inner;      // bt0, kt
            int o10 = o00 + 16384;            // bt1, kt
            aH[0] = ldcg(hH + o00); aH[1] = ldcg(hH + o10);
            aH[2] = ldcg(hH + o00 + 128); aH[3] = ldcg(hH + o10 + 128);
            aL[0] = ldcg(hL + o00); aL[1] = ldcg(hL + o10);
            aL[2] = ldcg(hL + o00 + 128); aL[3] = ldcg(hL + o10 + 128);
        };

        const float u0 = u_next;   // valid when m <= S_-2

        float acc[4][4];
#pragma unroll
        for (int nt = 0; nt < 4; ++nt)
#pragma unroll
            for (int q = 0; q < 4; ++q) acc[nt][q] = 0.f;

        unsigned aH[2][4], aL[2][4];
        loadfrag(0, aH[0], aL[0]);
#pragma unroll
        for (int s = 0; s < 4; ++s) {
            const int cur = s & 1;
            if (s < 3) loadfrag(s + 1, aH[cur ^ 1], aL[cur ^ 1]);
#pragma unroll
            for (int nt = 0; nt < 4; ++nt) {
                mma16816(acc[nt], aH[cur], Bhi[s][nt]);
                mma16816(acc[nt], aH[cur], Blo[s][nt]);
                mma16816(acc[nt], aL[cur], Bhi[s][nt]);
            }
        }

        // ---- store partials (padded stride -> conflict-free) ----
        {
            float* pw = part + w * (16 * PSTRIDE);
            int prow = l >> 2, pcol = (l & 3) << 1;
#pragma unroll
            for (int nt = 0; nt < 4; ++nt) {
                *(float2*)&pw[prow * PSTRIDE + nt * 8 + pcol] =
                    make_float2(acc[nt][0], acc[nt][1]);
                *(float2*)&pw[(prow + 8) * PSTRIDE + nt * 8 + pcol] =
                    make_float2(acc[nt][2], acc[nt][3]);
            }
        }
        __syncthreads();

        // ---- reduce 16 k-slices, bias, tanh, h write (bf16 hi/lo) ----
        float av;
        {
            float s = 0.f;
#pragma unroll
            for (int ww = 0; ww < 16; ++ww)
                s += part[ww * (16 * PSTRIDE) + rb * PSTRIDE + l];
            av = s + bhj;
            if (m <= S_ - 2) {
                float hv = tanhf(u0 + av);
                __nv_bfloat16 hi = __float2bfloat16(hv);
                __nv_bfloat16 lo = __float2bfloat16(hv - __bfloat162float(hi));
                int idx = HTILE_IDX(gb, j);
                g_hbf[(m + 1) & 1][0][idx] = hi;
                g_hbf[(m + 1) & 1][1][idx] = lo;
                if (m == S_ - 2) g_ht[gb * H_ + j] = hv;
            }
        }

        // z write target (tiled bf16, rows r = b*512 + t)
        const int zr = (gb << 9) + m;
        const long zt = ((long)(zr >> 3) * 128 + (j >> 3)) * 64
                      + ((zr & 7) << 3) + (j & 7);

        if (m != S_ - 1) {
            __syncthreads();
            if (tid == 0) {
                // fused release + arrival on this b-group's counter
                asm volatile("red.release.gpu.global.add.u32 [%0], %1;"
                             :: "l"(bar), "r"(1u) : "memory");
            }
            // barrier window: z tanh + bf16 store AND next-step U prefetch
            if (m >= 1) {
                float zv = tanhf(av);
                __nv_bfloat16 zh = __float2bfloat16(zv);
                g_zhi[zt] = zh;
                g_zlo[zt] = __float2bfloat16(zv - __bfloat162float(zh));
            }
            if (m + 1 <= S_ - 2)
                u_next = g_U[((long)(m + 1) * 64 + gb) * H_ + j];
            if (tid == 0) {
                unsigned target = (unsigned)(32 * (m + 1));
                unsigned v;
                do {
                    asm volatile("ld.acquire.gpu.global.u32 %0, [%1];"
                                 : "=r"(v) : "l"(bar));
                } while (v < target);
            }
            __syncthreads();
        } else {
            float zv = tanhf(av);
            __nv_bfloat16 zh = __float2bfloat16(zv);
            g_zhi[zt] = zh;
            g_zlo[zt] = __float2bfloat16(zv - __bfloat162float(zh));
        }
    }
}

// ---------------------------------------------------------------------------
// Row softmax over O_=512 cols; warp per row, logits read from g_U (reused).
// ---------------------------------------------------------------------------
__global__ __launch_bounds__(256) void softmax_k(float* __restrict__ out) {
    int r = blockIdx.x * 8 + (threadIdx.x >> 5);
    int l = threadIdx.x & 31;
    const float* row = g_U + (long)r * O_;

    float4 v[4];
    float mx = -3.0e38f;
#pragma unroll
    for (int q = 0; q < 4; ++q) {
        v[q] = *(const float4*)&row[(l + (q << 5)) << 2];
        mx = fmaxf(mx, fmaxf(fmaxf(v[q].x, v[q].y), fmaxf(v[q].z, v[q].w)));
    }
#pragma unroll
    for (int o = 16; o; o >>= 1) mx = fmaxf(mx, __shfl_xor_sync(~0u, mx, o));

    float s = 0.f;
#pragma unroll
    for (int q = 0; q < 4; ++q) {
        v[q].x = expf(v[q].x - mx); v[q].y = expf(v[q].y - mx);
        v[q].z = expf(v[q].z - mx); v[q].w = expf(v[q].w - mx);
        s += (v[q].x + v[q].y) + (v[q].z + v[q].w);
    }
#pragma unroll
    for (int o = 16; o; o >>= 1) s += __shfl_xor_sync(~0u, s, o);
    float inv = 1.0f / s;

#pragma unroll
    for (int q = 0; q < 4; ++q) {
        float4 wv = make_float4(v[q].x * inv, v[q].y * inv, v[q].z * inv, v[q].w * inv);
        *(float4*)&out[(long)r * O_ + ((l + (q << 5)) << 2)] = wv;
    }
}

__global__ void copyht_k(float* __restrict__ dst) {
    int i = blockIdx.x * blockDim.x + threadIdx.x;
    if (i < B_ * H_) dst[i] = g_ht[i];
}

// ---------------------------------------------------------------------------
// Launch (only harness pointers cross the host/device boundary)
// ---------------------------------------------------------------------------
extern "C" void kernel_launch(void* const* d_in, const int* in_sizes, int n_in,
                              void* d_out, int out_size) {
    const float* x  = (const float*)d_in[0];
    const float* h0 = (const float*)d_in[1];
    const float* Wi = (const float*)d_in[2];
    const float* bi = (const float*)d_in[3];
    const float* Wh = (const float*)d_in[4];
    const float* bh = (const float*)d_in[5];
    const float* W3 = (const float*)d_in[6];
    const float* b3 = (const float*)d_in[7];
    float* out = (float*)d_out;

    cudaFuncSetAttribute(recur_k, cudaFuncAttributeMaxDynamicSharedMemorySize,
                         RECUR_SMEM);

    // 1. init state + pre-convert operands to tiled bf16 hi/lo
    init_k<<<(B_ * H_ + 255) / 256, 256>>>(h0);
    cvt_x_k<<<(B_ * S_ * I_ / 4 + 255) / 256, 256>>>(x);
    cvt_w_k<H_, I_, 0><<<(H_ * I_ / 4 + 255) / 256, 256>>>(Wi);
    cvt_w_k<O_, H_, 1><<<(O_ * H_ / 4 + 255) / 256, 256>>>(W3);

    // 2. U[t][b][:] = x[b][t][:] @ Wi^T + bi   (t = 0..510)
    gemm_bf<0><<<dim3(H_ / 64, S_ - 1), 256>>>(bi);

    // 3. Serial recurrence (persistent, 128 CTAs, 512 steps, tensor cores)
    recur_k<<<128, 512, RECUR_SMEM>>>(Wh, bh);

    // 4. logits = Z @ W3^T + b3   (g_U reused as logits buffer)
    gemm_bf<1><<<dim3(O_ / 64, (B_ * S_) / 64), 256>>>(b3);

    // 5. softmax -> d_out
    softmax_k<<<(B_ * S_) / 8, 256>>>(out);

    // 6. final hidden state appended after softmax output
    if (out_size >= B_ * S_ * O_ + B_ * H_) {
        copyht_k<<<(B_ * H_ + 255) / 256, 256>>>(out + (long)B_ * S_ * O_);
    }
}